// round 10
// baseline (speedup 1.0000x reference)
#include <cuda_runtime.h>
#include <cuda_bf16.h>
#include <math.h>
#include <stdint.h>

#define BB 4
#define SS 2048
#define FF 512
#define HH 8
#define DD 64
#define HD 512
#define MT (BB*SS)   // 8192

// ---------------------------------------------------------------------------
// Scratch (static device globals = sanctioned scratch path)
// ---------------------------------------------------------------------------
__device__ __nv_bfloat16 g_Xh[MT*FF];
__device__ __nv_bfloat16 g_Xl[MT*FF];
__device__ __nv_bfloat16 g_Wh[3*HD*FF];
__device__ __nv_bfloat16 g_Wl[3*HD*FF];
__device__ __nv_bfloat16 g_Qh[BB*HH*SS*DD];
__device__ __nv_bfloat16 g_Ql[BB*HH*SS*DD];
__device__ __nv_bfloat16 g_Kh[BB*HH*SS*DD];
__device__ __nv_bfloat16 g_Kl[BB*HH*SS*DD];
__device__ __nv_bfloat16 g_Vth[BB*HH*DD*SS];   // transposed: [b,h,d,s]
__device__ __nv_bfloat16 g_Vtl[BB*HH*DD*SS];   // transposed: [b,h,d,s]
__device__ float g_zt[SS];                      // zt * log2(e)

// ---------------------------------------------------------------------------
// Helpers
// ---------------------------------------------------------------------------
__device__ __forceinline__ uint32_t smem_u32(const void* p) {
    uint32_t a;
    asm("{ .reg .u64 t; cvta.to.shared.u64 t, %1; cvt.u32.u64 %0, t; }"
        : "=r"(a) : "l"(p));
    return a;
}

#define CP_ASYNC16(dst, src) \
    asm volatile("cp.async.cg.shared.global [%0], [%1], 16;" \
        :: "r"(dst), "l"(src) : "memory")
#define CP_COMMIT() asm volatile("cp.async.commit_group;" ::: "memory")
#define CP_WAIT1()  asm volatile("cp.async.wait_group 1;" ::: "memory")

__device__ __forceinline__ void mma_bf16(float* d, const uint32_t* a, const uint32_t* b) {
    asm volatile(
        "mma.sync.aligned.m16n8k16.row.col.f32.bf16.bf16.f32 "
        "{%0,%1,%2,%3}, {%4,%5,%6,%7}, {%8,%9}, {%0,%1,%2,%3};"
        : "+f"(d[0]), "+f"(d[1]), "+f"(d[2]), "+f"(d[3])
        : "r"(a[0]), "r"(a[1]), "r"(a[2]), "r"(a[3]), "r"(b[0]), "r"(b[1]));
}

__device__ __forceinline__ void ldsm4(uint32_t* r, uint32_t addr) {
    asm volatile("ldmatrix.sync.aligned.m8n8.x4.shared.b16 {%0,%1,%2,%3}, [%4];"
        : "=r"(r[0]), "=r"(r[1]), "=r"(r[2]), "=r"(r[3]) : "r"(addr));
}

__device__ __forceinline__ uint32_t pk2(__nv_bfloat16 a, __nv_bfloat16 b) {
    return (uint32_t)__bfloat16_as_ushort(a) | ((uint32_t)__bfloat16_as_ushort(b) << 16);
}

__device__ __forceinline__ float ex2f(float x) {
    float y;
    asm("ex2.approx.f32 %0, %1;" : "=f"(y) : "f"(x));
    return y;
}

__device__ __forceinline__ uint32_t cvt_bf16x2(float hi, float lo) {
    uint32_t d;
    asm("cvt.rn.bf16x2.f32 %0, %1, %2;" : "=r"(d) : "f"(hi), "f"(lo));
    return d;
}

// ---------------------------------------------------------------------------
// z_hat table (log2-domain: includes 1/sqrt(D) and log2(e))
// ---------------------------------------------------------------------------
__global__ void zhat_kernel(const float* __restrict__ ah, const float* __restrict__ vh)
{
    int i = blockIdx.x * blockDim.x + threadIdx.x;
    if (i < SS) {
        float a = ah[0], v = vh[0];
        float z = 1.0f + expf(v) / (1.0f + expf(v - a * (float)i));
        g_zt[i] = z * 0.125f * 1.4426950408889634f;
    }
}

// ---------------------------------------------------------------------------
// Split X and W (fp32 -> bf16 hi + bf16 lo). 8 elems/thread, 16B stores.
// ---------------------------------------------------------------------------
#define NX8 (MT*FF/8)
#define NW8_1 (HD*FF/8)

__global__ __launch_bounds__(256) void split_kernel(
    const float* __restrict__ X, const float* __restrict__ Wq,
    const float* __restrict__ Wk, const float* __restrict__ Wv)
{
    int i = blockIdx.x * 256 + threadIdx.x;
    const float* src;
    __nv_bfloat16 *dh, *dl;
    int off;
    if (i < NX8) {
        src = X; off = i; dh = g_Xh; dl = g_Xl;
    } else {
        int j = i - NX8;
        int m = j >> 15;
        off = j & 32767;
        src = (m == 0) ? Wq : ((m == 1) ? Wk : Wv);
        dh = g_Wh + (size_t)m * HD * FF;
        dl = g_Wl + (size_t)m * HD * FF;
    }
    float4 v0 = ((const float4*)src)[(size_t)off * 2];
    float4 v1 = ((const float4*)src)[(size_t)off * 2 + 1];
    float f[8] = {v0.x, v0.y, v0.z, v0.w, v1.x, v1.y, v1.z, v1.w};
    __nv_bfloat16 h[8], l[8];
#pragma unroll
    for (int k = 0; k < 8; k++) {
        h[k] = __float2bfloat16(f[k]);
        l[k] = __float2bfloat16(f[k] - __bfloat162float(h[k]));
    }
    uint4 H, L;
    H.x = pk2(h[0], h[1]); H.y = pk2(h[2], h[3]);
    H.z = pk2(h[4], h[5]); H.w = pk2(h[6], h[7]);
    L.x = pk2(l[0], l[1]); L.y = pk2(l[2], l[3]);
    L.z = pk2(l[4], l[5]); L.w = pk2(l[6], l[7]);
    ((uint4*)dh)[off] = H;
    ((uint4*)dl)[off] = L;
}

// ---------------------------------------------------------------------------
// Fused QKV projection via mma.sync + ldmatrix, bf16x3, acc-major MMA order.
// (unchanged from R9)
// ---------------------------------------------------------------------------
#define PROW 144
#define PARR 18432
#define PSTG (4*PARR)
#define PROJ_SMEM (2*PSTG)

__global__ __launch_bounds__(256) void proj_mma(
    const float* __restrict__ bq, const float* __restrict__ bk,
    const float* __restrict__ bv)
{
    extern __shared__ char sm[];
    const uint32_t sbase = smem_u32(sm);
    const int tid = threadIdx.x;
    const int w = tid >> 5, lane = tid & 31;
    const int gr = lane >> 2, qt = lane & 3;
    const int nb = blockIdx.x;
    const int m0 = blockIdx.y * 128;

    const uint32_t rowoffB = (uint32_t)(((lane & 7) + ((lane >> 4) << 3)) * PROW
                                        + ((lane >> 3) & 1) * 16);
    const uint32_t rowoffA = (uint32_t)(((lane & 7) + (((lane >> 3) & 1) << 3)) * PROW
                                        + (lane >> 4) * 16);

    float acc[16][4];
#pragma unroll
    for (int i = 0; i < 16; i++)
#pragma unroll
        for (int j = 0; j < 4; j++) acc[i][j] = 0.f;

    auto fill = [&](int stg, int k0) {
        char* dstb = sm + stg * PSTG;
#pragma unroll
        for (int ii = 0; ii < 16; ii++) {
            int idx = ii * 256 + tid;
            int arr = idx >> 10;
            int r = (idx >> 3) & 127;
            int c = idx & 7;
            const __nv_bfloat16* src;
            if (arr == 0)      src = g_Xh + (size_t)(m0 + r) * FF + k0 + c * 8;
            else if (arr == 1) src = g_Xl + (size_t)(m0 + r) * FF + k0 + c * 8;
            else if (arr == 2) src = g_Wh + (size_t)(nb * 128 + r) * FF + k0 + c * 8;
            else               src = g_Wl + (size_t)(nb * 128 + r) * FF + k0 + c * 8;
            uint32_t d = smem_u32(dstb + arr * PARR + r * PROW + c * 16);
            CP_ASYNC16(d, src);
        }
        CP_COMMIT();
    };

    fill(0, 0);
    fill(1, 64);

    const uint32_t w16off = (uint32_t)(w * 16 * PROW);
#pragma unroll 1
    for (int ks = 0; ks < 8; ks++) {
        CP_WAIT1();
        __syncthreads();
        const uint32_t B   = sbase + (ks & 1) * PSTG;
        const uint32_t aXh = B;
        const uint32_t aXl = B + PARR;
        const uint32_t aWh = B + 2 * PARR;
        const uint32_t aWl = B + 3 * PARR;
#pragma unroll
        for (int kf = 0; kf < 4; kf++) {
            uint32_t xh[4], xl[4];
            ldsm4(xh, aXh + w16off + kf * 32 + rowoffA);
            ldsm4(xl, aXl + w16off + kf * 32 + rowoffA);
#pragma unroll
            for (int np = 0; np < 4; np++) {
                uint32_t wh0[4], wl0[4], wh1[4], wl1[4];
                ldsm4(wh0, aWh + (2 * np) * (16 * PROW) + kf * 32 + rowoffB);
                ldsm4(wl0, aWl + (2 * np) * (16 * PROW) + kf * 32 + rowoffB);
                ldsm4(wh1, aWh + (2 * np + 1) * (16 * PROW) + kf * 32 + rowoffB);
                ldsm4(wl1, aWl + (2 * np + 1) * (16 * PROW) + kf * 32 + rowoffB);
                float* a0 = acc[4 * np];
                float* a1 = acc[4 * np + 1];
                float* a2 = acc[4 * np + 2];
                float* a3 = acc[4 * np + 3];
                mma_bf16(a0, xh, &wh0[0]); mma_bf16(a1, xh, &wh0[2]);
                mma_bf16(a2, xh, &wh1[0]); mma_bf16(a3, xh, &wh1[2]);
                mma_bf16(a0, xh, &wl0[0]); mma_bf16(a1, xh, &wl0[2]);
                mma_bf16(a2, xh, &wl1[0]); mma_bf16(a3, xh, &wl1[2]);
                mma_bf16(a0, xl, &wh0[0]); mma_bf16(a1, xl, &wh0[2]);
                mma_bf16(a2, xl, &wh1[0]); mma_bf16(a3, xl, &wh1[2]);
            }
        }
        __syncthreads();
        if (ks + 2 < 8) fill(ks & 1, (ks + 2) * 64);
    }

    const int r0 = m0 + w * 16 + gr;
#pragma unroll
    for (int nf = 0; nf < 16; nf++) {
        int ng;
        {
            int np = nf >> 2, j = nf & 3;
            int nfp = 2 * np + (j >> 1);
            int oldnf = 2 * nfp + (j & 1);
            ng = nb * 128 + oldnf * 8 + qt * 2;
        }
        int sel = ng >> 9;
        int within = ng & 511;
        const float* bias = (sel == 0) ? bq : (sel == 1) ? bk : bv;
        float b0 = bias[within], b1 = bias[within + 1];
        int h = within >> 6, d = within & 63;
#pragma unroll
        for (int half = 0; half < 2; half++) {
            int m = r0 + half * 8;
            int bb = m >> 11, s = m & 2047;
            float y0 = acc[nf][half * 2 + 0] + b0;
            float y1 = acc[nf][half * 2 + 1] + b1;
            __nv_bfloat16 h0 = __float2bfloat16(y0);
            __nv_bfloat16 h1 = __float2bfloat16(y1);
            __nv_bfloat16 l0 = __float2bfloat16(y0 - __bfloat162float(h0));
            __nv_bfloat16 l1 = __float2bfloat16(y1 - __bfloat162float(h1));
            if (sel < 2) {
                __nv_bfloat16* dh = (sel == 0) ? g_Qh : g_Kh;
                __nv_bfloat16* dl = (sel == 0) ? g_Ql : g_Kl;
                size_t a = (((size_t)(bb * HH + h)) * SS + s) * DD + d;
                *(uint32_t*)&dh[a] = pk2(h0, h1);
                *(uint32_t*)&dl[a] = pk2(l0, l1);
            } else {
                size_t a0 = (((size_t)(bb * HH + h)) * DD + d) * SS + s;
                size_t a1 = a0 + SS;
                g_Vth[a0] = h0; g_Vth[a1] = h1;
                g_Vtl[a0] = l0; g_Vtl[a1] = l1;
            }
        }
    }
}

// ---------------------------------------------------------------------------
// Flash attention: m32 per warp (2 A-frag sets), 128 q-rows/CTA, 4 warps.
// B-frag smem traffic per unit work halved -> tensor-bound.
// 32-key tiles, 2-stage ring, 2 CTAs/SM.
// ---------------------------------------------------------------------------
#define NT 64
#define KROW 144
#define VROW 80
#define KARR (32*KROW)
#define VARR (64*VROW)
#define ASTG (2*KARR + 2*VARR)
#define AZT  (2*ASTG)
#define ATTN_SMEM (AZT + SS*4)

__global__ __launch_bounds__(128, 2) void attn_mma(float* __restrict__ out)
{
    extern __shared__ char sm[];
    const uint32_t sbase = smem_u32(sm);
    float* zts = (float*)(sm + AZT);
    const int tid = threadIdx.x;
    const int w = tid >> 5, lane = tid & 31;
    const int gr = lane >> 2, qt = lane & 3;
    const int bh = blockIdx.y;
    const int q0 = blockIdx.x * 128;

    const uint32_t rowK = (uint32_t)(((lane & 7) + ((lane >> 4) << 3)) * KROW
                                     + ((lane >> 3) & 1) * 16);
    const uint32_t rowV = (uint32_t)(((lane & 7) + ((lane >> 4) << 3)) * VROW
                                     + ((lane >> 3) & 1) * 16);

    for (int i = tid; i < SS; i += 128) zts[i] = g_zt[i];

    // two A-frag row sets: set s covers rows r0+16s, r0+16s+8
    const int r0 = q0 + w * 32 + gr;
    const __nv_bfloat16* Qh = g_Qh + (size_t)bh * SS * DD;
    const __nv_bfloat16* Ql = g_Ql + (size_t)bh * SS * DD;
    uint32_t qah[2][4][4], qal[2][4][4];
#pragma unroll
    for (int s = 0; s < 2; s++) {
        int ra = r0 + 16 * s;
#pragma unroll
        for (int kf = 0; kf < 4; kf++) {
            int col = kf * 16 + qt * 2;
            qah[s][kf][0] = *(const uint32_t*)(Qh + (size_t)ra * 64 + col);
            qah[s][kf][1] = *(const uint32_t*)(Qh + (size_t)(ra + 8) * 64 + col);
            qah[s][kf][2] = *(const uint32_t*)(Qh + (size_t)ra * 64 + col + 8);
            qah[s][kf][3] = *(const uint32_t*)(Qh + (size_t)(ra + 8) * 64 + col + 8);
            qal[s][kf][0] = *(const uint32_t*)(Ql + (size_t)ra * 64 + col);
            qal[s][kf][1] = *(const uint32_t*)(Ql + (size_t)(ra + 8) * 64 + col);
            qal[s][kf][2] = *(const uint32_t*)(Ql + (size_t)ra * 64 + col + 8);
            qal[s][kf][3] = *(const uint32_t*)(Ql + (size_t)(ra + 8) * 64 + col + 8);
        }
    }

    auto fill = [&](int slot, int k0) {
        char* dstb = sm + slot * ASTG;
#pragma unroll
        for (int ii = 0; ii < 8; ii++) {
            int idx = ii * 128 + tid;
            int arr = idx >> 8;
            const __nv_bfloat16* src;
            uint32_t d;
            if (arr < 2) {
                int r = (idx >> 3) & 31, c = idx & 7;
                src = ((arr == 0) ? g_Kh : g_Kl) + ((size_t)bh * SS + k0 + r) * 64 + c * 8;
                d = smem_u32(dstb + arr * KARR + r * KROW + c * 16);
            } else {
                int j = idx & 255;
                int r = j >> 2, c = j & 3;
                src = ((arr == 2) ? g_Vth : g_Vtl) + ((size_t)bh * DD + r) * SS + k0 + c * 8;
                d = smem_u32(dstb + 2 * KARR + (arr - 2) * VARR + r * VROW + c * 16);
            }
            CP_ASYNC16(d, src);
        }
        CP_COMMIT();
    };

    fill(0, 0);
    fill(1, 32);

    float O[2][8][4];
#pragma unroll
    for (int s = 0; s < 2; s++)
#pragma unroll
        for (int i = 0; i < 8; i++)
#pragma unroll
            for (int j = 0; j < 4; j++) O[s][i][j] = 0.f;
    float mreg[4] = {-1e30f, -1e30f, -1e30f, -1e30f};
    float lreg[4] = {0.f, 0.f, 0.f, 0.f};

#pragma unroll 1
    for (int kt = 0; kt < NT; kt++) {
        CP_WAIT1();
        __syncthreads();
        const uint32_t B    = sbase + (kt & 1) * ASTG;
        const uint32_t aKh  = B;
        const uint32_t aKl  = B + KARR;
        const uint32_t aVth = B + 2 * KARR;
        const uint32_t aVtl = B + 2 * KARR + VARR;
        const int k0 = kt * 32;

        // ---- S = Q K^T (bf16x3), both sets, acc-major (dep distance 8) ----
        float S[2][4][4];
#pragma unroll
        for (int s = 0; s < 2; s++)
#pragma unroll
            for (int i = 0; i < 4; i++)
#pragma unroll
                for (int j = 0; j < 4; j++) S[s][i][j] = 0.f;

#pragma unroll
        for (int kf = 0; kf < 4; kf++) {
            uint32_t rh0[4], rl0[4], rh1[4], rl1[4];
            ldsm4(rh0, aKh + kf * 32 + rowK);
            ldsm4(rl0, aKl + kf * 32 + rowK);
            ldsm4(rh1, aKh + 16 * KROW + kf * 32 + rowK);
            ldsm4(rl1, aKl + 16 * KROW + kf * 32 + rowK);
            // hh
            mma_bf16(S[0][0], qah[0][kf], &rh0[0]); mma_bf16(S[0][1], qah[0][kf], &rh0[2]);
            mma_bf16(S[0][2], qah[0][kf], &rh1[0]); mma_bf16(S[0][3], qah[0][kf], &rh1[2]);
            mma_bf16(S[1][0], qah[1][kf], &rh0[0]); mma_bf16(S[1][1], qah[1][kf], &rh0[2]);
            mma_bf16(S[1][2], qah[1][kf], &rh1[0]); mma_bf16(S[1][3], qah[1][kf], &rh1[2]);
            // hl
            mma_bf16(S[0][0], qah[0][kf], &rl0[0]); mma_bf16(S[0][1], qah[0][kf], &rl0[2]);
            mma_bf16(S[0][2], qah[0][kf], &rl1[0]); mma_bf16(S[0][3], qah[0][kf], &rl1[2]);
            mma_bf16(S[1][0], qah[1][kf], &rl0[0]); mma_bf16(S[1][1], qah[1][kf], &rl0[2]);
            mma_bf16(S[1][2], qah[1][kf], &rl1[0]); mma_bf16(S[1][3], qah[1][kf], &rl1[2]);
            // lh
            mma_bf16(S[0][0], qal[0][kf], &rh0[0]); mma_bf16(S[0][1], qal[0][kf], &rh0[2]);
            mma_bf16(S[0][2], qal[0][kf], &rh1[0]); mma_bf16(S[0][3], qal[0][kf], &rh1[2]);
            mma_bf16(S[1][0], qal[1][kf], &rh0[0]); mma_bf16(S[1][1], qal[1][kf], &rh0[2]);
            mma_bf16(S[1][2], qal[1][kf], &rh1[0]); mma_bf16(S[1][3], qal[1][kf], &rh1[2]);
        }

        // ---- per-set: softmax (rows disjoint) then PV ----
#pragma unroll
        for (int s = 0; s < 2; s++) {
            const int ra = r0 + 16 * s;
            float mt0 = -1e30f, mt1 = -1e30f;
#pragma unroll
            for (int nf = 0; nf < 4; nf++) {
                int c0 = k0 + nf * 8 + qt * 2;
                S[s][nf][0] *= zts[abs(ra - c0)];
                S[s][nf][1] *= zts[abs(ra - c0 - 1)];
                S[s][nf][2] *= zts[abs(ra + 8 - c0)];
                S[s][nf][3] *= zts[abs(ra + 8 - c0 - 1)];
                mt0 = fmaxf(mt0, fmaxf(S[s][nf][0], S[s][nf][1]));
                mt1 = fmaxf(mt1, fmaxf(S[s][nf][2], S[s][nf][3]));
            }
            mt0 = fmaxf(mt0, __shfl_xor_sync(0xffffffffu, mt0, 1));
            mt0 = fmaxf(mt0, __shfl_xor_sync(0xffffffffu, mt0, 2));
            mt1 = fmaxf(mt1, __shfl_xor_sync(0xffffffffu, mt1, 1));
            mt1 = fmaxf(mt1, __shfl_xor_sync(0xffffffffu, mt1, 2));
            bool changed = (mt0 > mreg[2 * s]) || (mt1 > mreg[2 * s + 1]);
            if (__any_sync(0xffffffffu, changed)) {
                float mn0 = fmaxf(mreg[2 * s], mt0), mn1 = fmaxf(mreg[2 * s + 1], mt1);
                float a0 = ex2f(mreg[2 * s] - mn0), a1 = ex2f(mreg[2 * s + 1] - mn1);
                mreg[2 * s] = mn0; mreg[2 * s + 1] = mn1;
                lreg[2 * s] *= a0; lreg[2 * s + 1] *= a1;
#pragma unroll
                for (int nf = 0; nf < 8; nf++) {
                    O[s][nf][0] *= a0; O[s][nf][1] *= a0;
                    O[s][nf][2] *= a1; O[s][nf][3] *= a1;
                }
            }

            float s0 = 0.f, s1 = 0.f;
            uint32_t ph[2][4], pl[2][4];
#pragma unroll
            for (int nf = 0; nf < 4; nf++) {
                float e0 = ex2f(S[s][nf][0] - mreg[2 * s]);
                float e1 = ex2f(S[s][nf][1] - mreg[2 * s]);
                float e2 = ex2f(S[s][nf][2] - mreg[2 * s + 1]);
                float e3 = ex2f(S[s][nf][3] - mreg[2 * s + 1]);
                s0 += e0 + e1; s1 += e2 + e3;
                uint32_t b0 = __float_as_uint(e0), b1 = __float_as_uint(e1);
                uint32_t b2 = __float_as_uint(e2), b3 = __float_as_uint(e3);
                uint32_t ph01 = __byte_perm(b0, b1, 0x7632);
                uint32_t ph23 = __byte_perm(b2, b3, 0x7632);
                float l0 = e0 - __uint_as_float(b0 & 0xffff0000u);
                float l1 = e1 - __uint_as_float(b1 & 0xffff0000u);
                float l2 = e2 - __uint_as_float(b2 & 0xffff0000u);
                float l3 = e3 - __uint_as_float(b3 & 0xffff0000u);
                uint32_t pl01 = cvt_bf16x2(l1, l0);
                uint32_t pl23 = cvt_bf16x2(l3, l2);
                int kf = nf >> 1;
                if ((nf & 1) == 0) {
                    ph[kf][0] = ph01; ph[kf][1] = ph23;
                    pl[kf][0] = pl01; pl[kf][1] = pl23;
                } else {
                    ph[kf][2] = ph01; ph[kf][3] = ph23;
                    pl[kf][2] = pl01; pl[kf][3] = pl23;
                }
            }
            lreg[2 * s] += s0;
            lreg[2 * s + 1] += s1;

            // PV for this set (acc-major, dep distance 4)
#pragma unroll
            for (int kf = 0; kf < 2; kf++) {
#pragma unroll
                for (int g = 0; g < 2; g++) {
                    uint32_t va0[4], vb0[4], va1[4], vb1[4];
                    ldsm4(va0, aVth + (2 * g) * (16 * VROW) + kf * 32 + rowV);
                    ldsm4(vb0, aVtl + (2 * g) * (16 * VROW) + kf * 32 + rowV);
                    ldsm4(va1, aVth + (2 * g + 1) * (16 * VROW) + kf * 32 + rowV);
                    ldsm4(vb1, aVtl + (2 * g + 1) * (16 * VROW) + kf * 32 + rowV);
                    float* o0 = O[s][4 * g];
                    float* o1 = O[s][4 * g + 1];
                    float* o2 = O[s][4 * g + 2];
                    float* o3 = O[s][4 * g + 3];
                    mma_bf16(o0, ph[kf], &va0[0]); mma_bf16(o1, ph[kf], &va0[2]);
                    mma_bf16(o2, ph[kf], &va1[0]); mma_bf16(o3, ph[kf], &va1[2]);
                    mma_bf16(o0, ph[kf], &vb0[0]); mma_bf16(o1, ph[kf], &vb0[2]);
                    mma_bf16(o2, ph[kf], &vb1[0]); mma_bf16(o3, ph[kf], &vb1[2]);
                    mma_bf16(o0, pl[kf], &va0[0]); mma_bf16(o1, pl[kf], &va0[2]);
                    mma_bf16(o2, pl[kf], &va1[0]); mma_bf16(o3, pl[kf], &va1[2]);
                }
            }
        }

        __syncthreads();
        if (kt + 2 < NT) fill(kt & 1, (kt + 2) * 32);
    }

    // ---- epilogue: quad-reduce l, normalize, store both sets ----
#pragma unroll
    for (int i = 0; i < 4; i++) {
        lreg[i] += __shfl_xor_sync(0xffffffffu, lreg[i], 1);
        lreg[i] += __shfl_xor_sync(0xffffffffu, lreg[i], 2);
    }
    int b = bh >> 3, h = bh & 7;
#pragma unroll
    for (int s = 0; s < 2; s++) {
        const int ra = r0 + 16 * s;
        float inv0 = 1.0f / lreg[2 * s], inv1 = 1.0f / lreg[2 * s + 1];
#pragma unroll
        for (int nf = 0; nf < 8; nf++) {
            int g = nf >> 2, j = nf & 3;
            int oldnf = 2 * (2 * g + (j >> 1)) + (j & 1);
            int d = oldnf * 8 + qt * 2;
            float2 o0 = make_float2(O[s][nf][0] * inv0, O[s][nf][1] * inv0);
            float2 o1 = make_float2(O[s][nf][2] * inv1, O[s][nf][3] * inv1);
            *(float2*)&out[((size_t)(b * SS) + ra) * HD + h * 64 + d]     = o0;
            *(float2*)&out[((size_t)(b * SS) + ra + 8) * HD + h * 64 + d] = o1;
        }
    }
}

// ---------------------------------------------------------------------------
extern "C" void kernel_launch(void* const* d_in, const int* in_sizes, int n_in,
                              void* d_out, int out_size)
{
    const float* x  = (const float*)d_in[0];
    const float* Wq = (const float*)d_in[1];
    const float* bq = (const float*)d_in[2];
    const float* Wk = (const float*)d_in[3];
    const float* bk = (const float*)d_in[4];
    const float* Wv = (const float*)d_in[5];
    const float* bv = (const float*)d_in[6];
    const float* ah = (const float*)d_in[7];
    const float* vh = (const float*)d_in[8];
    float* out = (float*)d_out;

    zhat_kernel<<<SS / 256, 256>>>(ah, vh);
    split_kernel<<<(NX8 + 3 * NW8_1) / 256, 256>>>(x, Wq, Wk, Wv);

    cudaFuncSetAttribute(proj_mma,
                         cudaFuncAttributeMaxDynamicSharedMemorySize, PROJ_SMEM);
    proj_mma<<<dim3(12, 64), 256, PROJ_SMEM>>>(bq, bk, bv);

    cudaFuncSetAttribute(attn_mma,
                         cudaFuncAttributeMaxDynamicSharedMemorySize, ATTN_SMEM);
    attn_mma<<<dim3(SS / 128, BB * HH), 128, ATTN_SMEM>>>(out);
}

// round 11
// speedup vs baseline: 1.1188x; 1.1188x over previous
#include <cuda_runtime.h>
#include <cuda_bf16.h>
#include <cuda_fp16.h>
#include <math.h>
#include <stdint.h>

#define BB 4
#define SS 2048
#define FF 512
#define HH 8
#define DD 64
#define HD 512
#define MT (BB*SS)   // 8192

// ---------------------------------------------------------------------------
// Scratch (static device globals = sanctioned scratch path)
// ---------------------------------------------------------------------------
__device__ __nv_bfloat16 g_Xh[MT*FF];
__device__ __nv_bfloat16 g_Xl[MT*FF];
__device__ __nv_bfloat16 g_Wh[3*HD*FF];
__device__ __nv_bfloat16 g_Wl[3*HD*FF];
__device__ __nv_bfloat16 g_Qh[BB*HH*SS*DD];
__device__ __nv_bfloat16 g_Ql[BB*HH*SS*DD];
__device__ __nv_bfloat16 g_Kh[BB*HH*SS*DD];
__device__ __nv_bfloat16 g_Kl[BB*HH*SS*DD];
__device__ __half g_Vth[BB*HH*DD*SS];   // transposed [b,h,d,s], fp16 hi
__device__ __half g_Vtl[BB*HH*DD*SS];   // transposed [b,h,d,s], fp16 lo
__device__ float g_zt[SS];              // zt * log2(e)

// ---------------------------------------------------------------------------
// Helpers
// ---------------------------------------------------------------------------
__device__ __forceinline__ uint32_t smem_u32(const void* p) {
    uint32_t a;
    asm("{ .reg .u64 t; cvta.to.shared.u64 t, %1; cvt.u32.u64 %0, t; }"
        : "=r"(a) : "l"(p));
    return a;
}

#define CP_ASYNC16(dst, src) \
    asm volatile("cp.async.cg.shared.global [%0], [%1], 16;" \
        :: "r"(dst), "l"(src) : "memory")
#define CP_COMMIT() asm volatile("cp.async.commit_group;" ::: "memory")
#define CP_WAIT1()  asm volatile("cp.async.wait_group 1;" ::: "memory")

__device__ __forceinline__ void mma_bf16(float* d, const uint32_t* a, const uint32_t* b) {
    asm volatile(
        "mma.sync.aligned.m16n8k16.row.col.f32.bf16.bf16.f32 "
        "{%0,%1,%2,%3}, {%4,%5,%6,%7}, {%8,%9}, {%0,%1,%2,%3};"
        : "+f"(d[0]), "+f"(d[1]), "+f"(d[2]), "+f"(d[3])
        : "r"(a[0]), "r"(a[1]), "r"(a[2]), "r"(a[3]), "r"(b[0]), "r"(b[1]));
}

__device__ __forceinline__ void mma_fp16(float* d, const uint32_t* a, const uint32_t* b) {
    asm volatile(
        "mma.sync.aligned.m16n8k16.row.col.f32.f16.f16.f32 "
        "{%0,%1,%2,%3}, {%4,%5,%6,%7}, {%8,%9}, {%0,%1,%2,%3};"
        : "+f"(d[0]), "+f"(d[1]), "+f"(d[2]), "+f"(d[3])
        : "r"(a[0]), "r"(a[1]), "r"(a[2]), "r"(a[3]), "r"(b[0]), "r"(b[1]));
}

__device__ __forceinline__ void ldsm4(uint32_t* r, uint32_t addr) {
    asm volatile("ldmatrix.sync.aligned.m8n8.x4.shared.b16 {%0,%1,%2,%3}, [%4];"
        : "=r"(r[0]), "=r"(r[1]), "=r"(r[2]), "=r"(r[3]) : "r"(addr));
}

__device__ __forceinline__ uint32_t pk2(__nv_bfloat16 a, __nv_bfloat16 b) {
    return (uint32_t)__bfloat16_as_ushort(a) | ((uint32_t)__bfloat16_as_ushort(b) << 16);
}

__device__ __forceinline__ float ex2f(float x) {
    float y;
    asm("ex2.approx.f32 %0, %1;" : "=f"(y) : "f"(x));
    return y;
}

// packs {lo=b, hi=a} as f16x2
__device__ __forceinline__ uint32_t cvt_f16x2(float hi, float lo) {
    uint32_t d;
    asm("cvt.rn.f16x2.f32 %0, %1, %2;" : "=r"(d) : "f"(hi), "f"(lo));
    return d;
}

// ---------------------------------------------------------------------------
// z_hat table (log2-domain: includes 1/sqrt(D) and log2(e))
// ---------------------------------------------------------------------------
__global__ void zhat_kernel(const float* __restrict__ ah, const float* __restrict__ vh)
{
    int i = blockIdx.x * blockDim.x + threadIdx.x;
    if (i < SS) {
        float a = ah[0], v = vh[0];
        float z = 1.0f + expf(v) / (1.0f + expf(v - a * (float)i));
        g_zt[i] = z * 0.125f * 1.4426950408889634f;
    }
}

// ---------------------------------------------------------------------------
// Split X and W (fp32 -> bf16 hi + bf16 lo). 8 elems/thread, 16B stores.
// ---------------------------------------------------------------------------
#define NX8 (MT*FF/8)
#define NW8_1 (HD*FF/8)

__global__ __launch_bounds__(256) void split_kernel(
    const float* __restrict__ X, const float* __restrict__ Wq,
    const float* __restrict__ Wk, const float* __restrict__ Wv)
{
    int i = blockIdx.x * 256 + threadIdx.x;
    const float* src;
    __nv_bfloat16 *dh, *dl;
    int off;
    if (i < NX8) {
        src = X; off = i; dh = g_Xh; dl = g_Xl;
    } else {
        int j = i - NX8;
        int m = j >> 15;
        off = j & 32767;
        src = (m == 0) ? Wq : ((m == 1) ? Wk : Wv);
        dh = g_Wh + (size_t)m * HD * FF;
        dl = g_Wl + (size_t)m * HD * FF;
    }
    float4 v0 = ((const float4*)src)[(size_t)off * 2];
    float4 v1 = ((const float4*)src)[(size_t)off * 2 + 1];
    float f[8] = {v0.x, v0.y, v0.z, v0.w, v1.x, v1.y, v1.z, v1.w};
    __nv_bfloat16 h[8], l[8];
#pragma unroll
    for (int k = 0; k < 8; k++) {
        h[k] = __float2bfloat16(f[k]);
        l[k] = __float2bfloat16(f[k] - __bfloat162float(h[k]));
    }
    uint4 H, L;
    H.x = pk2(h[0], h[1]); H.y = pk2(h[2], h[3]);
    H.z = pk2(h[4], h[5]); H.w = pk2(h[6], h[7]);
    L.x = pk2(l[0], l[1]); L.y = pk2(l[2], l[3]);
    L.z = pk2(l[4], l[5]); L.w = pk2(l[6], l[7]);
    ((uint4*)dh)[off] = H;
    ((uint4*)dl)[off] = L;
}

// ---------------------------------------------------------------------------
// Fused QKV projection via mma.sync + ldmatrix, bf16x3, acc-major MMA order.
// Q/K epilogue -> bf16 hi/lo [b,h,s,d]; V epilogue -> fp16 hi/lo [b,h,d,s].
// ---------------------------------------------------------------------------
#define PROW 144
#define PARR 18432
#define PSTG (4*PARR)
#define PROJ_SMEM (2*PSTG)

__global__ __launch_bounds__(256) void proj_mma(
    const float* __restrict__ bq, const float* __restrict__ bk,
    const float* __restrict__ bv)
{
    extern __shared__ char sm[];
    const uint32_t sbase = smem_u32(sm);
    const int tid = threadIdx.x;
    const int w = tid >> 5, lane = tid & 31;
    const int gr = lane >> 2, qt = lane & 3;
    const int nb = blockIdx.x;
    const int m0 = blockIdx.y * 128;

    const uint32_t rowoffB = (uint32_t)(((lane & 7) + ((lane >> 4) << 3)) * PROW
                                        + ((lane >> 3) & 1) * 16);
    const uint32_t rowoffA = (uint32_t)(((lane & 7) + (((lane >> 3) & 1) << 3)) * PROW
                                        + (lane >> 4) * 16);

    float acc[16][4];
#pragma unroll
    for (int i = 0; i < 16; i++)
#pragma unroll
        for (int j = 0; j < 4; j++) acc[i][j] = 0.f;

    auto fill = [&](int stg, int k0) {
        char* dstb = sm + stg * PSTG;
#pragma unroll
        for (int ii = 0; ii < 16; ii++) {
            int idx = ii * 256 + tid;
            int arr = idx >> 10;
            int r = (idx >> 3) & 127;
            int c = idx & 7;
            const __nv_bfloat16* src;
            if (arr == 0)      src = g_Xh + (size_t)(m0 + r) * FF + k0 + c * 8;
            else if (arr == 1) src = g_Xl + (size_t)(m0 + r) * FF + k0 + c * 8;
            else if (arr == 2) src = g_Wh + (size_t)(nb * 128 + r) * FF + k0 + c * 8;
            else               src = g_Wl + (size_t)(nb * 128 + r) * FF + k0 + c * 8;
            uint32_t d = smem_u32(dstb + arr * PARR + r * PROW + c * 16);
            CP_ASYNC16(d, src);
        }
        CP_COMMIT();
    };

    fill(0, 0);
    fill(1, 64);

    const uint32_t w16off = (uint32_t)(w * 16 * PROW);
#pragma unroll 1
    for (int ks = 0; ks < 8; ks++) {
        CP_WAIT1();
        __syncthreads();
        const uint32_t B   = sbase + (ks & 1) * PSTG;
        const uint32_t aXh = B;
        const uint32_t aXl = B + PARR;
        const uint32_t aWh = B + 2 * PARR;
        const uint32_t aWl = B + 3 * PARR;
#pragma unroll
        for (int kf = 0; kf < 4; kf++) {
            uint32_t xh[4], xl[4];
            ldsm4(xh, aXh + w16off + kf * 32 + rowoffA);
            ldsm4(xl, aXl + w16off + kf * 32 + rowoffA);
#pragma unroll
            for (int np = 0; np < 4; np++) {
                uint32_t wh0[4], wl0[4], wh1[4], wl1[4];
                ldsm4(wh0, aWh + (2 * np) * (16 * PROW) + kf * 32 + rowoffB);
                ldsm4(wl0, aWl + (2 * np) * (16 * PROW) + kf * 32 + rowoffB);
                ldsm4(wh1, aWh + (2 * np + 1) * (16 * PROW) + kf * 32 + rowoffB);
                ldsm4(wl1, aWl + (2 * np + 1) * (16 * PROW) + kf * 32 + rowoffB);
                float* a0 = acc[4 * np];
                float* a1 = acc[4 * np + 1];
                float* a2 = acc[4 * np + 2];
                float* a3 = acc[4 * np + 3];
                mma_bf16(a0, xh, &wh0[0]); mma_bf16(a1, xh, &wh0[2]);
                mma_bf16(a2, xh, &wh1[0]); mma_bf16(a3, xh, &wh1[2]);
                mma_bf16(a0, xh, &wl0[0]); mma_bf16(a1, xh, &wl0[2]);
                mma_bf16(a2, xh, &wl1[0]); mma_bf16(a3, xh, &wl1[2]);
                mma_bf16(a0, xl, &wh0[0]); mma_bf16(a1, xl, &wh0[2]);
                mma_bf16(a2, xl, &wh1[0]); mma_bf16(a3, xl, &wh1[2]);
            }
        }
        __syncthreads();
        if (ks + 2 < 8) fill(ks & 1, (ks + 2) * 64);
    }

    const int r0 = m0 + w * 16 + gr;
#pragma unroll
    for (int nf = 0; nf < 16; nf++) {
        int ng;
        {
            int np = nf >> 2, j = nf & 3;
            int nfp = 2 * np + (j >> 1);
            int oldnf = 2 * nfp + (j & 1);
            ng = nb * 128 + oldnf * 8 + qt * 2;
        }
        int sel = ng >> 9;
        int within = ng & 511;
        const float* bias = (sel == 0) ? bq : (sel == 1) ? bk : bv;
        float b0 = bias[within], b1 = bias[within + 1];
        int h = within >> 6, d = within & 63;
#pragma unroll
        for (int half = 0; half < 2; half++) {
            int m = r0 + half * 8;
            int bb = m >> 11, s = m & 2047;
            float y0 = acc[nf][half * 2 + 0] + b0;
            float y1 = acc[nf][half * 2 + 1] + b1;
            if (sel < 2) {
                __nv_bfloat16 h0 = __float2bfloat16(y0);
                __nv_bfloat16 h1 = __float2bfloat16(y1);
                __nv_bfloat16 l0 = __float2bfloat16(y0 - __bfloat162float(h0));
                __nv_bfloat16 l1 = __float2bfloat16(y1 - __bfloat162float(h1));
                __nv_bfloat16* dh = (sel == 0) ? g_Qh : g_Kh;
                __nv_bfloat16* dl = (sel == 0) ? g_Ql : g_Kl;
                size_t a = (((size_t)(bb * HH + h)) * SS + s) * DD + d;
                *(uint32_t*)&dh[a] = pk2(h0, h1);
                *(uint32_t*)&dl[a] = pk2(l0, l1);
            } else {
                __half h0 = __float2half_rn(y0);
                __half h1 = __float2half_rn(y1);
                __half l0 = __float2half_rn(y0 - __half2float(h0));
                __half l1 = __float2half_rn(y1 - __half2float(h1));
                size_t a0 = (((size_t)(bb * HH + h)) * DD + d) * SS + s;
                size_t a1 = a0 + SS;
                g_Vth[a0] = h0; g_Vth[a1] = h1;
                g_Vtl[a0] = l0; g_Vtl[a1] = l1;
            }
        }
    }
}

// ---------------------------------------------------------------------------
// Flash attention: S = bf16x3 (3 MMAs), PV = fp16 P x (Vh+Vl) (2 MMAs).
// 128 threads (4 warps, 64 q-rows), 32-key tiles, 2-stage ring, 4 CTAs/SM.
// ---------------------------------------------------------------------------
#define NT 64
#define KROW 144
#define VROW 80
#define KARR (32*KROW)
#define VARR (64*VROW)
#define ASTG (2*KARR + 2*VARR)
#define AZT  (2*ASTG)
#define ATTN_SMEM (AZT + SS*4)

__global__ __launch_bounds__(128, 4) void attn_mma(float* __restrict__ out)
{
    extern __shared__ char sm[];
    const uint32_t sbase = smem_u32(sm);
    float* zts = (float*)(sm + AZT);
    const int tid = threadIdx.x;
    const int w = tid >> 5, lane = tid & 31;
    const int gr = lane >> 2, qt = lane & 3;
    const int bh = blockIdx.y;
    const int q0 = blockIdx.x * 64;

    const uint32_t rowK = (uint32_t)(((lane & 7) + ((lane >> 4) << 3)) * KROW
                                     + ((lane >> 3) & 1) * 16);
    const uint32_t rowV = (uint32_t)(((lane & 7) + ((lane >> 4) << 3)) * VROW
                                     + ((lane >> 3) & 1) * 16);

    for (int i = tid; i < SS; i += 128) zts[i] = g_zt[i];

    const int r0 = q0 + w * 16 + gr;
    const __nv_bfloat16* Qh = g_Qh + (size_t)bh * SS * DD;
    const __nv_bfloat16* Ql = g_Ql + (size_t)bh * SS * DD;
    uint32_t qah[4][4], qal[4][4];
#pragma unroll
    for (int kf = 0; kf < 4; kf++) {
        int col = kf * 16 + qt * 2;
        qah[kf][0] = *(const uint32_t*)(Qh + (size_t)r0 * 64 + col);
        qah[kf][1] = *(const uint32_t*)(Qh + (size_t)(r0 + 8) * 64 + col);
        qah[kf][2] = *(const uint32_t*)(Qh + (size_t)r0 * 64 + col + 8);
        qah[kf][3] = *(const uint32_t*)(Qh + (size_t)(r0 + 8) * 64 + col + 8);
        qal[kf][0] = *(const uint32_t*)(Ql + (size_t)r0 * 64 + col);
        qal[kf][1] = *(const uint32_t*)(Ql + (size_t)(r0 + 8) * 64 + col);
        qal[kf][2] = *(const uint32_t*)(Ql + (size_t)r0 * 64 + col + 8);
        qal[kf][3] = *(const uint32_t*)(Ql + (size_t)(r0 + 8) * 64 + col + 8);
    }

    auto fill = [&](int slot, int k0) {
        char* dstb = sm + slot * ASTG;
#pragma unroll
        for (int ii = 0; ii < 8; ii++) {
            int idx = ii * 128 + tid;
            int arr = idx >> 8;
            uint32_t d;
            if (arr < 2) {
                int r = (idx >> 3) & 31, c = idx & 7;
                const __nv_bfloat16* src =
                    ((arr == 0) ? g_Kh : g_Kl) + ((size_t)bh * SS + k0 + r) * 64 + c * 8;
                d = smem_u32(dstb + arr * KARR + r * KROW + c * 16);
                CP_ASYNC16(d, src);
            } else {
                int j = idx & 255;
                int r = j >> 2, c = j & 3;
                const __half* src =
                    ((arr == 2) ? g_Vth : g_Vtl) + ((size_t)bh * DD + r) * SS + k0 + c * 8;
                d = smem_u32(dstb + 2 * KARR + (arr - 2) * VARR + r * VROW + c * 16);
                CP_ASYNC16(d, src);
            }
        }
        CP_COMMIT();
    };

    fill(0, 0);
    fill(1, 32);

    float O[8][4];
#pragma unroll
    for (int i = 0; i < 8; i++)
#pragma unroll
        for (int j = 0; j < 4; j++) O[i][j] = 0.f;
    float m0r = -1e30f, m1r = -1e30f, l0r = 0.f, l1r = 0.f;

#pragma unroll 1
    for (int kt = 0; kt < NT; kt++) {
        CP_WAIT1();
        __syncthreads();
        const uint32_t B    = sbase + (kt & 1) * ASTG;
        const uint32_t aKh  = B;
        const uint32_t aKl  = B + KARR;
        const uint32_t aVth = B + 2 * KARR;
        const uint32_t aVtl = B + 2 * KARR + VARR;
        const int k0 = kt * 32;

        // ---- S = Q K^T (bf16x3), acc-major order ----
        float S[4][4];
#pragma unroll
        for (int i = 0; i < 4; i++)
#pragma unroll
            for (int j = 0; j < 4; j++) S[i][j] = 0.f;

#pragma unroll
        for (int kf = 0; kf < 4; kf++) {
            uint32_t rh0[4], rl0[4], rh1[4], rl1[4];
            ldsm4(rh0, aKh + kf * 32 + rowK);
            ldsm4(rl0, aKl + kf * 32 + rowK);
            ldsm4(rh1, aKh + 16 * KROW + kf * 32 + rowK);
            ldsm4(rl1, aKl + 16 * KROW + kf * 32 + rowK);
            mma_bf16(S[0], qah[kf], &rh0[0]); mma_bf16(S[1], qah[kf], &rh0[2]);
            mma_bf16(S[2], qah[kf], &rh1[0]); mma_bf16(S[3], qah[kf], &rh1[2]);
            mma_bf16(S[0], qah[kf], &rl0[0]); mma_bf16(S[1], qah[kf], &rl0[2]);
            mma_bf16(S[2], qah[kf], &rl1[0]); mma_bf16(S[3], qah[kf], &rl1[2]);
            mma_bf16(S[0], qal[kf], &rh0[0]); mma_bf16(S[1], qal[kf], &rh0[2]);
            mma_bf16(S[2], qal[kf], &rh1[0]); mma_bf16(S[3], qal[kf], &rh1[2]);
        }

        // ---- bias + online softmax (log2 domain, lazy rescale) ----
        float mt0 = -1e30f, mt1 = -1e30f;
#pragma unroll
        for (int nf = 0; nf < 4; nf++) {
            int c0 = k0 + nf * 8 + qt * 2;
            S[nf][0] *= zts[abs(r0 - c0)];
            S[nf][1] *= zts[abs(r0 - c0 - 1)];
            S[nf][2] *= zts[abs(r0 + 8 - c0)];
            S[nf][3] *= zts[abs(r0 + 8 - c0 - 1)];
            mt0 = fmaxf(mt0, fmaxf(S[nf][0], S[nf][1]));
            mt1 = fmaxf(mt1, fmaxf(S[nf][2], S[nf][3]));
        }
        mt0 = fmaxf(mt0, __shfl_xor_sync(0xffffffffu, mt0, 1));
        mt0 = fmaxf(mt0, __shfl_xor_sync(0xffffffffu, mt0, 2));
        mt1 = fmaxf(mt1, __shfl_xor_sync(0xffffffffu, mt1, 1));
        mt1 = fmaxf(mt1, __shfl_xor_sync(0xffffffffu, mt1, 2));
        bool changed = (mt0 > m0r) || (mt1 > m1r);
        if (__any_sync(0xffffffffu, changed)) {
            float mn0 = fmaxf(m0r, mt0), mn1 = fmaxf(m1r, mt1);
            float a0 = ex2f(m0r - mn0), a1 = ex2f(m1r - mn1);
            m0r = mn0; m1r = mn1;
            l0r *= a0; l1r *= a1;
#pragma unroll
            for (int nf = 0; nf < 8; nf++) {
                O[nf][0] *= a0; O[nf][1] *= a0;
                O[nf][2] *= a1; O[nf][3] *= a1;
            }
        }

        float s0 = 0.f, s1 = 0.f;
        uint32_t ph[2][4];
#pragma unroll
        for (int nf = 0; nf < 4; nf++) {
            float e0 = ex2f(S[nf][0] - m0r);
            float e1 = ex2f(S[nf][1] - m0r);
            float e2 = ex2f(S[nf][2] - m1r);
            float e3 = ex2f(S[nf][3] - m1r);
            s0 += e0 + e1; s1 += e2 + e3;
            uint32_t p01 = cvt_f16x2(e1, e0);
            uint32_t p23 = cvt_f16x2(e3, e2);
            int kf = nf >> 1;
            if ((nf & 1) == 0) { ph[kf][0] = p01; ph[kf][1] = p23; }
            else               { ph[kf][2] = p01; ph[kf][3] = p23; }
        }
        l0r += s0;      // per-thread partial; quad-reduced at epilogue
        l1r += s1;

        // ---- O += P V (fp16, 2 terms), acc-major order ----
#pragma unroll
        for (int kf = 0; kf < 2; kf++) {
#pragma unroll
            for (int g = 0; g < 2; g++) {
                uint32_t va0[4], vb0[4], va1[4], vb1[4];
                ldsm4(va0, aVth + (2 * g) * (16 * VROW) + kf * 32 + rowV);
                ldsm4(vb0, aVtl + (2 * g) * (16 * VROW) + kf * 32 + rowV);
                ldsm4(va1, aVth + (2 * g + 1) * (16 * VROW) + kf * 32 + rowV);
                ldsm4(vb1, aVtl + (2 * g + 1) * (16 * VROW) + kf * 32 + rowV);
                float* o0 = O[4 * g];
                float* o1 = O[4 * g + 1];
                float* o2 = O[4 * g + 2];
                float* o3 = O[4 * g + 3];
                // P x Vh
                mma_fp16(o0, ph[kf], &va0[0]); mma_fp16(o1, ph[kf], &va0[2]);
                mma_fp16(o2, ph[kf], &va1[0]); mma_fp16(o3, ph[kf], &va1[2]);
                // P x Vl
                mma_fp16(o0, ph[kf], &vb0[0]); mma_fp16(o1, ph[kf], &vb0[2]);
                mma_fp16(o2, ph[kf], &vb1[0]); mma_fp16(o3, ph[kf], &vb1[2]);
            }
        }

        __syncthreads();
        if (kt + 2 < NT) fill(kt & 1, (kt + 2) * 32);
    }

    // ---- epilogue: quad-reduce l, normalize, store ----
    l0r += __shfl_xor_sync(0xffffffffu, l0r, 1);
    l0r += __shfl_xor_sync(0xffffffffu, l0r, 2);
    l1r += __shfl_xor_sync(0xffffffffu, l1r, 1);
    l1r += __shfl_xor_sync(0xffffffffu, l1r, 2);
    float inv0 = 1.0f / l0r, inv1 = 1.0f / l1r;
    int b = bh >> 3, h = bh & 7;
#pragma unroll
    for (int nf = 0; nf < 8; nf++) {
        int g = nf >> 2, j = nf & 3;
        int oldnf = 2 * (2 * g + (j >> 1)) + (j & 1);
        int d = oldnf * 8 + qt * 2;
        float2 o0 = make_float2(O[nf][0] * inv0, O[nf][1] * inv0);
        float2 o1 = make_float2(O[nf][2] * inv1, O[nf][3] * inv1);
        *(float2*)&out[((size_t)(b * SS) + r0) * HD + h * 64 + d]       = o0;
        *(float2*)&out[((size_t)(b * SS) + r0 + 8) * HD + h * 64 + d]   = o1;
    }
}

// ---------------------------------------------------------------------------
extern "C" void kernel_launch(void* const* d_in, const int* in_sizes, int n_in,
                              void* d_out, int out_size)
{
    const float* x  = (const float*)d_in[0];
    const float* Wq = (const float*)d_in[1];
    const float* bq = (const float*)d_in[2];
    const float* Wk = (const float*)d_in[3];
    const float* bk = (const float*)d_in[4];
    const float* Wv = (const float*)d_in[5];
    const float* bv = (const float*)d_in[6];
    const float* ah = (const float*)d_in[7];
    const float* vh = (const float*)d_in[8];
    float* out = (float*)d_out;

    zhat_kernel<<<SS / 256, 256>>>(ah, vh);
    split_kernel<<<(NX8 + 3 * NW8_1) / 256, 256>>>(x, Wq, Wk, Wv);

    cudaFuncSetAttribute(proj_mma,
                         cudaFuncAttributeMaxDynamicSharedMemorySize, PROJ_SMEM);
    proj_mma<<<dim3(12, 64), 256, PROJ_SMEM>>>(bq, bk, bv);

    cudaFuncSetAttribute(attn_mma,
                         cudaFuncAttributeMaxDynamicSharedMemorySize, ATTN_SMEM);
    attn_mma<<<dim3(SS / 64, BB * HH), 128, ATTN_SMEM>>>(out);
}

// round 12
// speedup vs baseline: 1.2715x; 1.1364x over previous
#include <cuda_runtime.h>
#include <cuda_bf16.h>
#include <cuda_fp16.h>
#include <math.h>
#include <stdint.h>

#define BB 4
#define SS 2048
#define FF 512
#define HH 8
#define DD 64
#define HD 512
#define MT (BB*SS)   // 8192

// ---------------------------------------------------------------------------
// Scratch (static device globals = sanctioned scratch path)
// ---------------------------------------------------------------------------
__device__ __nv_bfloat16 g_Xh[MT*FF];
__device__ __nv_bfloat16 g_Xl[MT*FF];
__device__ __nv_bfloat16 g_Wh[3*HD*FF];
__device__ __nv_bfloat16 g_Wl[3*HD*FF];
__device__ __nv_bfloat16 g_Qh[BB*HH*SS*DD];
__device__ __nv_bfloat16 g_Ql[BB*HH*SS*DD];
__device__ __nv_bfloat16 g_Kh[BB*HH*SS*DD];
__device__ __nv_bfloat16 g_Kl[BB*HH*SS*DD];
__device__ __half g_Vth[BB*HH*DD*SS];   // transposed [b,h,d,s], fp16
__device__ float g_zt[SS];              // zt * log2(e)

// ---------------------------------------------------------------------------
// Helpers
// ---------------------------------------------------------------------------
__device__ __forceinline__ uint32_t smem_u32(const void* p) {
    uint32_t a;
    asm("{ .reg .u64 t; cvta.to.shared.u64 t, %1; cvt.u32.u64 %0, t; }"
        : "=r"(a) : "l"(p));
    return a;
}

#define CP_ASYNC16(dst, src) \
    asm volatile("cp.async.cg.shared.global [%0], [%1], 16;" \
        :: "r"(dst), "l"(src) : "memory")
#define CP_COMMIT() asm volatile("cp.async.commit_group;" ::: "memory")
#define CP_WAIT1()  asm volatile("cp.async.wait_group 1;" ::: "memory")

__device__ __forceinline__ void mma_bf16(float* d, const uint32_t* a, const uint32_t* b) {
    asm volatile(
        "mma.sync.aligned.m16n8k16.row.col.f32.bf16.bf16.f32 "
        "{%0,%1,%2,%3}, {%4,%5,%6,%7}, {%8,%9}, {%0,%1,%2,%3};"
        : "+f"(d[0]), "+f"(d[1]), "+f"(d[2]), "+f"(d[3])
        : "r"(a[0]), "r"(a[1]), "r"(a[2]), "r"(a[3]), "r"(b[0]), "r"(b[1]));
}

__device__ __forceinline__ void mma_fp16(float* d, const uint32_t* a, const uint32_t* b) {
    asm volatile(
        "mma.sync.aligned.m16n8k16.row.col.f32.f16.f16.f32 "
        "{%0,%1,%2,%3}, {%4,%5,%6,%7}, {%8,%9}, {%0,%1,%2,%3};"
        : "+f"(d[0]), "+f"(d[1]), "+f"(d[2]), "+f"(d[3])
        : "r"(a[0]), "r"(a[1]), "r"(a[2]), "r"(a[3]), "r"(b[0]), "r"(b[1]));
}

__device__ __forceinline__ void ldsm4(uint32_t* r, uint32_t addr) {
    asm volatile("ldmatrix.sync.aligned.m8n8.x4.shared.b16 {%0,%1,%2,%3}, [%4];"
        : "=r"(r[0]), "=r"(r[1]), "=r"(r[2]), "=r"(r[3]) : "r"(addr));
}

__device__ __forceinline__ uint32_t pk2(__nv_bfloat16 a, __nv_bfloat16 b) {
    return (uint32_t)__bfloat16_as_ushort(a) | ((uint32_t)__bfloat16_as_ushort(b) << 16);
}

__device__ __forceinline__ float ex2f(float x) {
    float y;
    asm("ex2.approx.f32 %0, %1;" : "=f"(y) : "f"(x));
    return y;
}

// packs {lo, hi} as f16x2
__device__ __forceinline__ uint32_t cvt_f16x2(float hi, float lo) {
    uint32_t d;
    asm("cvt.rn.f16x2.f32 %0, %1, %2;" : "=r"(d) : "f"(hi), "f"(lo));
    return d;
}

// ---------------------------------------------------------------------------
// z_hat table (log2-domain: includes 1/sqrt(D) and log2(e))
// ---------------------------------------------------------------------------
__global__ void zhat_kernel(const float* __restrict__ ah, const float* __restrict__ vh)
{
    int i = blockIdx.x * blockDim.x + threadIdx.x;
    if (i < SS) {
        float a = ah[0], v = vh[0];
        float z = 1.0f + expf(v) / (1.0f + expf(v - a * (float)i));
        g_zt[i] = z * 0.125f * 1.4426950408889634f;
    }
}

// ---------------------------------------------------------------------------
// Split X and W (fp32 -> bf16 hi + bf16 lo). 8 elems/thread, 16B stores.
// ---------------------------------------------------------------------------
#define NX8 (MT*FF/8)
#define NW8_1 (HD*FF/8)

__global__ __launch_bounds__(256) void split_kernel(
    const float* __restrict__ X, const float* __restrict__ Wq,
    const float* __restrict__ Wk, const float* __restrict__ Wv)
{
    int i = blockIdx.x * 256 + threadIdx.x;
    const float* src;
    __nv_bfloat16 *dh, *dl;
    int off;
    if (i < NX8) {
        src = X; off = i; dh = g_Xh; dl = g_Xl;
    } else {
        int j = i - NX8;
        int m = j >> 15;
        off = j & 32767;
        src = (m == 0) ? Wq : ((m == 1) ? Wk : Wv);
        dh = g_Wh + (size_t)m * HD * FF;
        dl = g_Wl + (size_t)m * HD * FF;
    }
    float4 v0 = ((const float4*)src)[(size_t)off * 2];
    float4 v1 = ((const float4*)src)[(size_t)off * 2 + 1];
    float f[8] = {v0.x, v0.y, v0.z, v0.w, v1.x, v1.y, v1.z, v1.w};
    __nv_bfloat16 h[8], l[8];
#pragma unroll
    for (int k = 0; k < 8; k++) {
        h[k] = __float2bfloat16(f[k]);
        l[k] = __float2bfloat16(f[k] - __bfloat162float(h[k]));
    }
    uint4 H, L;
    H.x = pk2(h[0], h[1]); H.y = pk2(h[2], h[3]);
    H.z = pk2(h[4], h[5]); H.w = pk2(h[6], h[7]);
    L.x = pk2(l[0], l[1]); L.y = pk2(l[2], l[3]);
    L.z = pk2(l[4], l[5]); L.w = pk2(l[6], l[7]);
    ((uint4*)dh)[off] = H;
    ((uint4*)dl)[off] = L;
}

// ---------------------------------------------------------------------------
// Fused QKV projection via mma.sync + ldmatrix, bf16x3, acc-major MMA order.
// Q/K epilogue -> bf16 hi/lo [b,h,s,d]; V epilogue -> fp16 [b,h,d,s].
// ---------------------------------------------------------------------------
#define PROW 144
#define PARR 18432
#define PSTG (4*PARR)
#define PROJ_SMEM (2*PSTG)

__global__ __launch_bounds__(256) void proj_mma(
    const float* __restrict__ bq, const float* __restrict__ bk,
    const float* __restrict__ bv)
{
    extern __shared__ char sm[];
    const uint32_t sbase = smem_u32(sm);
    const int tid = threadIdx.x;
    const int w = tid >> 5, lane = tid & 31;
    const int gr = lane >> 2, qt = lane & 3;
    const int nb = blockIdx.x;
    const int m0 = blockIdx.y * 128;

    const uint32_t rowoffB = (uint32_t)(((lane & 7) + ((lane >> 4) << 3)) * PROW
                                        + ((lane >> 3) & 1) * 16);
    const uint32_t rowoffA = (uint32_t)(((lane & 7) + (((lane >> 3) & 1) << 3)) * PROW
                                        + (lane >> 4) * 16);

    float acc[16][4];
#pragma unroll
    for (int i = 0; i < 16; i++)
#pragma unroll
        for (int j = 0; j < 4; j++) acc[i][j] = 0.f;

    auto fill = [&](int stg, int k0) {
        char* dstb = sm + stg * PSTG;
#pragma unroll
        for (int ii = 0; ii < 16; ii++) {
            int idx = ii * 256 + tid;
            int arr = idx >> 10;
            int r = (idx >> 3) & 127;
            int c = idx & 7;
            const __nv_bfloat16* src;
            if (arr == 0)      src = g_Xh + (size_t)(m0 + r) * FF + k0 + c * 8;
            else if (arr == 1) src = g_Xl + (size_t)(m0 + r) * FF + k0 + c * 8;
            else if (arr == 2) src = g_Wh + (size_t)(nb * 128 + r) * FF + k0 + c * 8;
            else               src = g_Wl + (size_t)(nb * 128 + r) * FF + k0 + c * 8;
            uint32_t d = smem_u32(dstb + arr * PARR + r * PROW + c * 16);
            CP_ASYNC16(d, src);
        }
        CP_COMMIT();
    };

    fill(0, 0);
    fill(1, 64);

    const uint32_t w16off = (uint32_t)(w * 16 * PROW);
#pragma unroll 1
    for (int ks = 0; ks < 8; ks++) {
        CP_WAIT1();
        __syncthreads();
        const uint32_t B   = sbase + (ks & 1) * PSTG;
        const uint32_t aXh = B;
        const uint32_t aXl = B + PARR;
        const uint32_t aWh = B + 2 * PARR;
        const uint32_t aWl = B + 3 * PARR;
#pragma unroll
        for (int kf = 0; kf < 4; kf++) {
            uint32_t xh[4], xl[4];
            ldsm4(xh, aXh + w16off + kf * 32 + rowoffA);
            ldsm4(xl, aXl + w16off + kf * 32 + rowoffA);
#pragma unroll
            for (int np = 0; np < 4; np++) {
                uint32_t wh0[4], wl0[4], wh1[4], wl1[4];
                ldsm4(wh0, aWh + (2 * np) * (16 * PROW) + kf * 32 + rowoffB);
                ldsm4(wl0, aWl + (2 * np) * (16 * PROW) + kf * 32 + rowoffB);
                ldsm4(wh1, aWh + (2 * np + 1) * (16 * PROW) + kf * 32 + rowoffB);
                ldsm4(wl1, aWl + (2 * np + 1) * (16 * PROW) + kf * 32 + rowoffB);
                float* a0 = acc[4 * np];
                float* a1 = acc[4 * np + 1];
                float* a2 = acc[4 * np + 2];
                float* a3 = acc[4 * np + 3];
                mma_bf16(a0, xh, &wh0[0]); mma_bf16(a1, xh, &wh0[2]);
                mma_bf16(a2, xh, &wh1[0]); mma_bf16(a3, xh, &wh1[2]);
                mma_bf16(a0, xh, &wl0[0]); mma_bf16(a1, xh, &wl0[2]);
                mma_bf16(a2, xh, &wl1[0]); mma_bf16(a3, xh, &wl1[2]);
                mma_bf16(a0, xl, &wh0[0]); mma_bf16(a1, xl, &wh0[2]);
                mma_bf16(a2, xl, &wh1[0]); mma_bf16(a3, xl, &wh1[2]);
            }
        }
        __syncthreads();
        if (ks + 2 < 8) fill(ks & 1, (ks + 2) * 64);
    }

    const int r0 = m0 + w * 16 + gr;
#pragma unroll
    for (int nf = 0; nf < 16; nf++) {
        int ng;
        {
            int np = nf >> 2, j = nf & 3;
            int nfp = 2 * np + (j >> 1);
            int oldnf = 2 * nfp + (j & 1);
            ng = nb * 128 + oldnf * 8 + qt * 2;
        }
        int sel = ng >> 9;
        int within = ng & 511;
        const float* bias = (sel == 0) ? bq : (sel == 1) ? bk : bv;
        float b0 = bias[within], b1 = bias[within + 1];
        int h = within >> 6, d = within & 63;
#pragma unroll
        for (int half = 0; half < 2; half++) {
            int m = r0 + half * 8;
            int bb = m >> 11, s = m & 2047;
            float y0 = acc[nf][half * 2 + 0] + b0;
            float y1 = acc[nf][half * 2 + 1] + b1;
            if (sel < 2) {
                __nv_bfloat16 h0 = __float2bfloat16(y0);
                __nv_bfloat16 h1 = __float2bfloat16(y1);
                __nv_bfloat16 l0 = __float2bfloat16(y0 - __bfloat162float(h0));
                __nv_bfloat16 l1 = __float2bfloat16(y1 - __bfloat162float(h1));
                __nv_bfloat16* dh = (sel == 0) ? g_Qh : g_Kh;
                __nv_bfloat16* dl = (sel == 0) ? g_Ql : g_Kl;
                size_t a = (((size_t)(bb * HH + h)) * SS + s) * DD + d;
                *(uint32_t*)&dh[a] = pk2(h0, h1);
                *(uint32_t*)&dl[a] = pk2(l0, l1);
            } else {
                size_t a0 = (((size_t)(bb * HH + h)) * DD + d) * SS + s;
                g_Vth[a0]      = __float2half_rn(y0);
                g_Vth[a0 + SS] = __float2half_rn(y1);
            }
        }
    }
}

// ---------------------------------------------------------------------------
// Flash attention: S = bf16x3 (3 MMAs), PV = fp16 P x V (1 MMA).
// 128 threads (4 warps, 64 q-rows), 32-key tiles, 2-stage ring, 4 CTAs/SM.
// ---------------------------------------------------------------------------
#define NT 64
#define KROW 144
#define VROW 80
#define KARR (32*KROW)          // 4608
#define VARR (64*VROW)          // 5120
#define ASTG (2*KARR + VARR)    // 14336
#define AZT  (2*ASTG)           // 28672
#define ATTN_SMEM (AZT + SS*4)  // 36864

__global__ __launch_bounds__(128, 4) void attn_mma(float* __restrict__ out)
{
    extern __shared__ char sm[];
    const uint32_t sbase = smem_u32(sm);
    float* zts = (float*)(sm + AZT);
    const int tid = threadIdx.x;
    const int w = tid >> 5, lane = tid & 31;
    const int gr = lane >> 2, qt = lane & 3;
    const int bh = blockIdx.y;
    const int q0 = blockIdx.x * 64;

    const uint32_t rowK = (uint32_t)(((lane & 7) + ((lane >> 4) << 3)) * KROW
                                     + ((lane >> 3) & 1) * 16);
    const uint32_t rowV = (uint32_t)(((lane & 7) + ((lane >> 4) << 3)) * VROW
                                     + ((lane >> 3) & 1) * 16);

    for (int i = tid; i < SS; i += 128) zts[i] = g_zt[i];

    const int r0 = q0 + w * 16 + gr;
    const __nv_bfloat16* Qh = g_Qh + (size_t)bh * SS * DD;
    const __nv_bfloat16* Ql = g_Ql + (size_t)bh * SS * DD;
    uint32_t qah[4][4], qal[4][4];
#pragma unroll
    for (int kf = 0; kf < 4; kf++) {
        int col = kf * 16 + qt * 2;
        qah[kf][0] = *(const uint32_t*)(Qh + (size_t)r0 * 64 + col);
        qah[kf][1] = *(const uint32_t*)(Qh + (size_t)(r0 + 8) * 64 + col);
        qah[kf][2] = *(const uint32_t*)(Qh + (size_t)r0 * 64 + col + 8);
        qah[kf][3] = *(const uint32_t*)(Qh + (size_t)(r0 + 8) * 64 + col + 8);
        qal[kf][0] = *(const uint32_t*)(Ql + (size_t)r0 * 64 + col);
        qal[kf][1] = *(const uint32_t*)(Ql + (size_t)(r0 + 8) * 64 + col);
        qal[kf][2] = *(const uint32_t*)(Ql + (size_t)r0 * 64 + col + 8);
        qal[kf][3] = *(const uint32_t*)(Ql + (size_t)(r0 + 8) * 64 + col + 8);
    }

    auto fill = [&](int slot, int k0) {
        char* dstb = sm + slot * ASTG;
#pragma unroll
        for (int ii = 0; ii < 6; ii++) {
            int idx = ii * 128 + tid;       // 0..767
            int arr = idx >> 8;             // 0,1 = Kh/Kl; 2 = V
            uint32_t d;
            if (arr < 2) {
                int r = (idx >> 3) & 31, c = idx & 7;
                const __nv_bfloat16* src =
                    ((arr == 0) ? g_Kh : g_Kl) + ((size_t)bh * SS + k0 + r) * 64 + c * 8;
                d = smem_u32(dstb + arr * KARR + r * KROW + c * 16);
                CP_ASYNC16(d, src);
            } else {
                int j = idx & 255;
                int r = j >> 2, c = j & 3;
                const __half* src =
                    g_Vth + ((size_t)bh * DD + r) * SS + k0 + c * 8;
                d = smem_u32(dstb + 2 * KARR + r * VROW + c * 16);
                CP_ASYNC16(d, src);
            }
        }
        CP_COMMIT();
    };

    fill(0, 0);
    fill(1, 32);

    float O[8][4];
#pragma unroll
    for (int i = 0; i < 8; i++)
#pragma unroll
        for (int j = 0; j < 4; j++) O[i][j] = 0.f;
    float m0r = -1e30f, m1r = -1e30f, l0r = 0.f, l1r = 0.f;

#pragma unroll 1
    for (int kt = 0; kt < NT; kt++) {
        CP_WAIT1();
        __syncthreads();
        const uint32_t B    = sbase + (kt & 1) * ASTG;
        const uint32_t aKh  = B;
        const uint32_t aKl  = B + KARR;
        const uint32_t aVth = B + 2 * KARR;
        const int k0 = kt * 32;

        // ---- S = Q K^T (bf16x3), acc-major order ----
        float S[4][4];
#pragma unroll
        for (int i = 0; i < 4; i++)
#pragma unroll
            for (int j = 0; j < 4; j++) S[i][j] = 0.f;

#pragma unroll
        for (int kf = 0; kf < 4; kf++) {
            uint32_t rh0[4], rl0[4], rh1[4], rl1[4];
            ldsm4(rh0, aKh + kf * 32 + rowK);
            ldsm4(rl0, aKl + kf * 32 + rowK);
            ldsm4(rh1, aKh + 16 * KROW + kf * 32 + rowK);
            ldsm4(rl1, aKl + 16 * KROW + kf * 32 + rowK);
            mma_bf16(S[0], qah[kf], &rh0[0]); mma_bf16(S[1], qah[kf], &rh0[2]);
            mma_bf16(S[2], qah[kf], &rh1[0]); mma_bf16(S[3], qah[kf], &rh1[2]);
            mma_bf16(S[0], qah[kf], &rl0[0]); mma_bf16(S[1], qah[kf], &rl0[2]);
            mma_bf16(S[2], qah[kf], &rl1[0]); mma_bf16(S[3], qah[kf], &rl1[2]);
            mma_bf16(S[0], qal[kf], &rh0[0]); mma_bf16(S[1], qal[kf], &rh0[2]);
            mma_bf16(S[2], qal[kf], &rh1[0]); mma_bf16(S[3], qal[kf], &rh1[2]);
        }

        // ---- bias + online softmax (log2 domain, lazy rescale) ----
        float mt0 = -1e30f, mt1 = -1e30f;
#pragma unroll
        for (int nf = 0; nf < 4; nf++) {
            int c0 = k0 + nf * 8 + qt * 2;
            S[nf][0] *= zts[abs(r0 - c0)];
            S[nf][1] *= zts[abs(r0 - c0 - 1)];
            S[nf][2] *= zts[abs(r0 + 8 - c0)];
            S[nf][3] *= zts[abs(r0 + 8 - c0 - 1)];
            mt0 = fmaxf(mt0, fmaxf(S[nf][0], S[nf][1]));
            mt1 = fmaxf(mt1, fmaxf(S[nf][2], S[nf][3]));
        }
        mt0 = fmaxf(mt0, __shfl_xor_sync(0xffffffffu, mt0, 1));
        mt0 = fmaxf(mt0, __shfl_xor_sync(0xffffffffu, mt0, 2));
        mt1 = fmaxf(mt1, __shfl_xor_sync(0xffffffffu, mt1, 1));
        mt1 = fmaxf(mt1, __shfl_xor_sync(0xffffffffu, mt1, 2));
        bool changed = (mt0 > m0r) || (mt1 > m1r);
        if (__any_sync(0xffffffffu, changed)) {
            float mn0 = fmaxf(m0r, mt0), mn1 = fmaxf(m1r, mt1);
            float a0 = ex2f(m0r - mn0), a1 = ex2f(m1r - mn1);
            m0r = mn0; m1r = mn1;
            l0r *= a0; l1r *= a1;
#pragma unroll
            for (int nf = 0; nf < 8; nf++) {
                O[nf][0] *= a0; O[nf][1] *= a0;
                O[nf][2] *= a1; O[nf][3] *= a1;
            }
        }

        float s0 = 0.f, s1 = 0.f;
        uint32_t ph[2][4];
#pragma unroll
        for (int nf = 0; nf < 4; nf++) {
            float e0 = ex2f(S[nf][0] - m0r);
            float e1 = ex2f(S[nf][1] - m0r);
            float e2 = ex2f(S[nf][2] - m1r);
            float e3 = ex2f(S[nf][3] - m1r);
            s0 += e0 + e1; s1 += e2 + e3;
            uint32_t p01 = cvt_f16x2(e1, e0);
            uint32_t p23 = cvt_f16x2(e3, e2);
            int kf = nf >> 1;
            if ((nf & 1) == 0) { ph[kf][0] = p01; ph[kf][1] = p23; }
            else               { ph[kf][2] = p01; ph[kf][3] = p23; }
        }
        l0r += s0;
        l1r += s1;

        // ---- O += P V (fp16, 1 term), acc-major order ----
#pragma unroll
        for (int kf = 0; kf < 2; kf++) {
#pragma unroll
            for (int g = 0; g < 2; g++) {
                uint32_t va0[4], va1[4];
                ldsm4(va0, aVth + (2 * g) * (16 * VROW) + kf * 32 + rowV);
                ldsm4(va1, aVth + (2 * g + 1) * (16 * VROW) + kf * 32 + rowV);
                float* o0 = O[4 * g];
                float* o1 = O[4 * g + 1];
                float* o2 = O[4 * g + 2];
                float* o3 = O[4 * g + 3];
                mma_fp16(o0, ph[kf], &va0[0]); mma_fp16(o1, ph[kf], &va0[2]);
                mma_fp16(o2, ph[kf], &va1[0]); mma_fp16(o3, ph[kf], &va1[2]);
            }
        }

        __syncthreads();
        if (kt + 2 < NT) fill(kt & 1, (kt + 2) * 32);
    }

    // ---- epilogue: quad-reduce l, normalize, store ----
    l0r += __shfl_xor_sync(0xffffffffu, l0r, 1);
    l0r += __shfl_xor_sync(0xffffffffu, l0r, 2);
    l1r += __shfl_xor_sync(0xffffffffu, l1r, 1);
    l1r += __shfl_xor_sync(0xffffffffu, l1r, 2);
    float inv0 = 1.0f / l0r, inv1 = 1.0f / l1r;
    int b = bh >> 3, h = bh & 7;
#pragma unroll
    for (int nf = 0; nf < 8; nf++) {
        int g = nf >> 2, j = nf & 3;
        int oldnf = 2 * (2 * g + (j >> 1)) + (j & 1);
        int d = oldnf * 8 + qt * 2;
        float2 o0 = make_float2(O[nf][0] * inv0, O[nf][1] * inv0);
        float2 o1 = make_float2(O[nf][2] * inv1, O[nf][3] * inv1);
        *(float2*)&out[((size_t)(b * SS) + r0) * HD + h * 64 + d]       = o0;
        *(float2*)&out[((size_t)(b * SS) + r0 + 8) * HD + h * 64 + d]   = o1;
    }
}

// ---------------------------------------------------------------------------
extern "C" void kernel_launch(void* const* d_in, const int* in_sizes, int n_in,
                              void* d_out, int out_size)
{
    const float* x  = (const float*)d_in[0];
    const float* Wq = (const float*)d_in[1];
    const float* bq = (const float*)d_in[2];
    const float* Wk = (const float*)d_in[3];
    const float* bk = (const float*)d_in[4];
    const float* Wv = (const float*)d_in[5];
    const float* bv = (const float*)d_in[6];
    const float* ah = (const float*)d_in[7];
    const float* vh = (const float*)d_in[8];
    float* out = (float*)d_out;

    zhat_kernel<<<SS / 256, 256>>>(ah, vh);
    split_kernel<<<(NX8 + 3 * NW8_1) / 256, 256>>>(x, Wq, Wk, Wv);

    cudaFuncSetAttribute(proj_mma,
                         cudaFuncAttributeMaxDynamicSharedMemorySize, PROJ_SMEM);
    proj_mma<<<dim3(12, 64), 256, PROJ_SMEM>>>(bq, bk, bv);

    cudaFuncSetAttribute(attn_mma,
                         cudaFuncAttributeMaxDynamicSharedMemorySize, ATTN_SMEM);
    attn_mma<<<dim3(SS / 64, BB * HH), 128, ATTN_SMEM>>>(out);
}

// round 13
// speedup vs baseline: 1.3521x; 1.0635x over previous
#include <cuda_runtime.h>
#include <cuda_bf16.h>
#include <cuda_fp16.h>
#include <math.h>
#include <stdint.h>

#define BB 4
#define SS 2048
#define FF 512
#define HH 8
#define DD 64
#define HD 512
#define MT (BB*SS)   // 8192

// ---------------------------------------------------------------------------
// Scratch (static device globals = sanctioned scratch path)
// ---------------------------------------------------------------------------
__device__ __nv_bfloat16 g_Xh[MT*FF];
__device__ __nv_bfloat16 g_Xl[MT*FF];
__device__ __half        g_X16[MT*FF];     // fp16 X (for V projection)
__device__ __nv_bfloat16 g_Wh[2*HD*FF];    // Wq, Wk hi
__device__ __nv_bfloat16 g_Wl[2*HD*FF];    // Wq, Wk lo
__device__ __half        g_Wv16[HD*FF];    // fp16 Wv
__device__ __nv_bfloat16 g_Qh[BB*HH*SS*DD];
__device__ __nv_bfloat16 g_Ql[BB*HH*SS*DD];
__device__ __nv_bfloat16 g_Kh[BB*HH*SS*DD];
__device__ __nv_bfloat16 g_Kl[BB*HH*SS*DD];
__device__ __half g_Vth[BB*HH*DD*SS];   // transposed [b,h,d,s], fp16
__device__ float g_zt[SS];              // zt * log2(e)

// ---------------------------------------------------------------------------
// Helpers
// ---------------------------------------------------------------------------
__device__ __forceinline__ uint32_t smem_u32(const void* p) {
    uint32_t a;
    asm("{ .reg .u64 t; cvta.to.shared.u64 t, %1; cvt.u32.u64 %0, t; }"
        : "=r"(a) : "l"(p));
    return a;
}

#define CP_ASYNC16(dst, src) \
    asm volatile("cp.async.cg.shared.global [%0], [%1], 16;" \
        :: "r"(dst), "l"(src) : "memory")
#define CP_COMMIT() asm volatile("cp.async.commit_group;" ::: "memory")
#define CP_WAIT1()  asm volatile("cp.async.wait_group 1;" ::: "memory")

__device__ __forceinline__ void mma_bf16(float* d, const uint32_t* a, const uint32_t* b) {
    asm volatile(
        "mma.sync.aligned.m16n8k16.row.col.f32.bf16.bf16.f32 "
        "{%0,%1,%2,%3}, {%4,%5,%6,%7}, {%8,%9}, {%0,%1,%2,%3};"
        : "+f"(d[0]), "+f"(d[1]), "+f"(d[2]), "+f"(d[3])
        : "r"(a[0]), "r"(a[1]), "r"(a[2]), "r"(a[3]), "r"(b[0]), "r"(b[1]));
}

__device__ __forceinline__ void mma_fp16(float* d, const uint32_t* a, const uint32_t* b) {
    asm volatile(
        "mma.sync.aligned.m16n8k16.row.col.f32.f16.f16.f32 "
        "{%0,%1,%2,%3}, {%4,%5,%6,%7}, {%8,%9}, {%0,%1,%2,%3};"
        : "+f"(d[0]), "+f"(d[1]), "+f"(d[2]), "+f"(d[3])
        : "r"(a[0]), "r"(a[1]), "r"(a[2]), "r"(a[3]), "r"(b[0]), "r"(b[1]));
}

__device__ __forceinline__ void ldsm4(uint32_t* r, uint32_t addr) {
    asm volatile("ldmatrix.sync.aligned.m8n8.x4.shared.b16 {%0,%1,%2,%3}, [%4];"
        : "=r"(r[0]), "=r"(r[1]), "=r"(r[2]), "=r"(r[3]) : "r"(addr));
}

__device__ __forceinline__ uint32_t pk2(__nv_bfloat16 a, __nv_bfloat16 b) {
    return (uint32_t)__bfloat16_as_ushort(a) | ((uint32_t)__bfloat16_as_ushort(b) << 16);
}

__device__ __forceinline__ uint32_t pk2h(__half a, __half b) {
    return (uint32_t)__half_as_ushort(a) | ((uint32_t)__half_as_ushort(b) << 16);
}

__device__ __forceinline__ float ex2f(float x) {
    float y;
    asm("ex2.approx.f32 %0, %1;" : "=f"(y) : "f"(x));
    return y;
}

// packs {lo, hi} as f16x2
__device__ __forceinline__ uint32_t cvt_f16x2(float hi, float lo) {
    uint32_t d;
    asm("cvt.rn.f16x2.f32 %0, %1, %2;" : "=r"(d) : "f"(hi), "f"(lo));
    return d;
}

// ---------------------------------------------------------------------------
// z_hat table (log2-domain: includes 1/sqrt(D) and log2(e))
// ---------------------------------------------------------------------------
__global__ void zhat_kernel(const float* __restrict__ ah, const float* __restrict__ vh)
{
    int i = blockIdx.x * blockDim.x + threadIdx.x;
    if (i < SS) {
        float a = ah[0], v = vh[0];
        float z = 1.0f + expf(v) / (1.0f + expf(v - a * (float)i));
        g_zt[i] = z * 0.125f * 1.4426950408889634f;
    }
}

// ---------------------------------------------------------------------------
// Split: X -> bf16 hi/lo + fp16; Wq/Wk -> bf16 hi/lo; Wv -> fp16.
// 8 elems/thread, 16B stores.
// ---------------------------------------------------------------------------
#define NX8 (MT*FF/8)
#define NW8_1 (HD*FF/8)

__global__ __launch_bounds__(256) void split_kernel(
    const float* __restrict__ X, const float* __restrict__ Wq,
    const float* __restrict__ Wk, const float* __restrict__ Wv)
{
    int i = blockIdx.x * 256 + threadIdx.x;
    if (i < NX8) {
        int off = i;
        float4 v0 = ((const float4*)X)[(size_t)off * 2];
        float4 v1 = ((const float4*)X)[(size_t)off * 2 + 1];
        float f[8] = {v0.x, v0.y, v0.z, v0.w, v1.x, v1.y, v1.z, v1.w};
        __nv_bfloat16 h[8], l[8];
        __half p[8];
#pragma unroll
        for (int k = 0; k < 8; k++) {
            h[k] = __float2bfloat16(f[k]);
            l[k] = __float2bfloat16(f[k] - __bfloat162float(h[k]));
            p[k] = __float2half_rn(f[k]);
        }
        uint4 H, L, P;
        H.x = pk2(h[0], h[1]); H.y = pk2(h[2], h[3]);
        H.z = pk2(h[4], h[5]); H.w = pk2(h[6], h[7]);
        L.x = pk2(l[0], l[1]); L.y = pk2(l[2], l[3]);
        L.z = pk2(l[4], l[5]); L.w = pk2(l[6], l[7]);
        P.x = pk2h(p[0], p[1]); P.y = pk2h(p[2], p[3]);
        P.z = pk2h(p[4], p[5]); P.w = pk2h(p[6], p[7]);
        ((uint4*)g_Xh)[off] = H;
        ((uint4*)g_Xl)[off] = L;
        ((uint4*)g_X16)[off] = P;
    } else {
        int j = i - NX8;
        int m = j >> 15;           // 0=Wq, 1=Wk, 2=Wv
        int off = j & 32767;
        const float* src = (m == 0) ? Wq : ((m == 1) ? Wk : Wv);
        float4 v0 = ((const float4*)src)[(size_t)off * 2];
        float4 v1 = ((const float4*)src)[(size_t)off * 2 + 1];
        float f[8] = {v0.x, v0.y, v0.z, v0.w, v1.x, v1.y, v1.z, v1.w};
        if (m < 2) {
            __nv_bfloat16 h[8], l[8];
#pragma unroll
            for (int k = 0; k < 8; k++) {
                h[k] = __float2bfloat16(f[k]);
                l[k] = __float2bfloat16(f[k] - __bfloat162float(h[k]));
            }
            uint4 H, L;
            H.x = pk2(h[0], h[1]); H.y = pk2(h[2], h[3]);
            H.z = pk2(h[4], h[5]); H.w = pk2(h[6], h[7]);
            L.x = pk2(l[0], l[1]); L.y = pk2(l[2], l[3]);
            L.z = pk2(l[4], l[5]); L.w = pk2(l[6], l[7]);
            size_t o = (size_t)m * NW8_1 + off;
            ((uint4*)g_Wh)[o] = H;
            ((uint4*)g_Wl)[o] = L;
        } else {
            __half p[8];
#pragma unroll
            for (int k = 0; k < 8; k++) p[k] = __float2half_rn(f[k]);
            uint4 P;
            P.x = pk2h(p[0], p[1]); P.y = pk2h(p[2], p[3]);
            P.z = pk2h(p[4], p[5]); P.w = pk2h(p[6], p[7]);
            ((uint4*)g_Wv16)[off] = P;
        }
    }
}

// ---------------------------------------------------------------------------
// Fused QKV projection. nb<8: Q/K via bf16x3. nb>=8: V via single fp16 MMA.
// Q/K epilogue -> bf16 hi/lo [b,h,s,d]; V epilogue -> fp16 [b,h,d,s].
// ---------------------------------------------------------------------------
#define PROW 144
#define PARR 18432
#define PSTG (4*PARR)
#define PROJ_SMEM (2*PSTG)

__global__ __launch_bounds__(256) void proj_mma(
    const float* __restrict__ bq, const float* __restrict__ bk,
    const float* __restrict__ bv)
{
    extern __shared__ char sm[];
    const uint32_t sbase = smem_u32(sm);
    const int tid = threadIdx.x;
    const int w = tid >> 5, lane = tid & 31;
    const int gr = lane >> 2, qt = lane & 3;
    const int nb = blockIdx.x;          // 0..11
    const int m0 = blockIdx.y * 128;

    const uint32_t rowoffB = (uint32_t)(((lane & 7) + ((lane >> 4) << 3)) * PROW
                                        + ((lane >> 3) & 1) * 16);
    const uint32_t rowoffA = (uint32_t)(((lane & 7) + (((lane >> 3) & 1) << 3)) * PROW
                                        + (lane >> 4) * 16);

    float acc[16][4];
#pragma unroll
    for (int i = 0; i < 16; i++)
#pragma unroll
        for (int j = 0; j < 4; j++) acc[i][j] = 0.f;

    const uint32_t w16off = (uint32_t)(w * 16 * PROW);

    if (nb < 8) {
        // ------------------- Q/K path: bf16x3 -------------------
        auto fill = [&](int stg, int k0) {
            char* dstb = sm + stg * PSTG;
#pragma unroll
            for (int ii = 0; ii < 16; ii++) {
                int idx = ii * 256 + tid;
                int arr = idx >> 10;
                int r = (idx >> 3) & 127;
                int c = idx & 7;
                const __nv_bfloat16* src;
                if (arr == 0)      src = g_Xh + (size_t)(m0 + r) * FF + k0 + c * 8;
                else if (arr == 1) src = g_Xl + (size_t)(m0 + r) * FF + k0 + c * 8;
                else if (arr == 2) src = g_Wh + (size_t)(nb * 128 + r) * FF + k0 + c * 8;
                else               src = g_Wl + (size_t)(nb * 128 + r) * FF + k0 + c * 8;
                uint32_t d = smem_u32(dstb + arr * PARR + r * PROW + c * 16);
                CP_ASYNC16(d, src);
            }
            CP_COMMIT();
        };

        fill(0, 0);
        fill(1, 64);

#pragma unroll 1
        for (int ks = 0; ks < 8; ks++) {
            CP_WAIT1();
            __syncthreads();
            const uint32_t B   = sbase + (ks & 1) * PSTG;
            const uint32_t aXh = B;
            const uint32_t aXl = B + PARR;
            const uint32_t aWh = B + 2 * PARR;
            const uint32_t aWl = B + 3 * PARR;
#pragma unroll
            for (int kf = 0; kf < 4; kf++) {
                uint32_t xh[4], xl[4];
                ldsm4(xh, aXh + w16off + kf * 32 + rowoffA);
                ldsm4(xl, aXl + w16off + kf * 32 + rowoffA);
#pragma unroll
                for (int np = 0; np < 4; np++) {
                    uint32_t wh0[4], wl0[4], wh1[4], wl1[4];
                    ldsm4(wh0, aWh + (2 * np) * (16 * PROW) + kf * 32 + rowoffB);
                    ldsm4(wl0, aWl + (2 * np) * (16 * PROW) + kf * 32 + rowoffB);
                    ldsm4(wh1, aWh + (2 * np + 1) * (16 * PROW) + kf * 32 + rowoffB);
                    ldsm4(wl1, aWl + (2 * np + 1) * (16 * PROW) + kf * 32 + rowoffB);
                    float* a0 = acc[4 * np];
                    float* a1 = acc[4 * np + 1];
                    float* a2 = acc[4 * np + 2];
                    float* a3 = acc[4 * np + 3];
                    mma_bf16(a0, xh, &wh0[0]); mma_bf16(a1, xh, &wh0[2]);
                    mma_bf16(a2, xh, &wh1[0]); mma_bf16(a3, xh, &wh1[2]);
                    mma_bf16(a0, xh, &wl0[0]); mma_bf16(a1, xh, &wl0[2]);
                    mma_bf16(a2, xh, &wl1[0]); mma_bf16(a3, xh, &wl1[2]);
                    mma_bf16(a0, xl, &wh0[0]); mma_bf16(a1, xl, &wh0[2]);
                    mma_bf16(a2, xl, &wh1[0]); mma_bf16(a3, xl, &wh1[2]);
                }
            }
            __syncthreads();
            if (ks + 2 < 8) fill(ks & 1, (ks + 2) * 64);
        }
    } else {
        // ------------------- V path: single fp16 MMA -------------------
        auto fillv = [&](int stg, int k0) {
            char* dstb = sm + stg * PSTG;
#pragma unroll
            for (int ii = 0; ii < 8; ii++) {
                int idx = ii * 256 + tid;       // 0..2047
                int arr = idx >> 10;            // 0: X16, 1: Wv16
                int r = (idx >> 3) & 127;
                int c = idx & 7;
                const __half* src = (arr == 0)
                    ? g_X16 + (size_t)(m0 + r) * FF + k0 + c * 8
                    : g_Wv16 + (size_t)((nb - 8) * 128 + r) * FF + k0 + c * 8;
                uint32_t d = smem_u32(dstb + arr * PARR + r * PROW + c * 16);
                CP_ASYNC16(d, src);
            }
            CP_COMMIT();
        };

        fillv(0, 0);
        fillv(1, 64);

#pragma unroll 1
        for (int ks = 0; ks < 8; ks++) {
            CP_WAIT1();
            __syncthreads();
            const uint32_t B   = sbase + (ks & 1) * PSTG;
            const uint32_t aX  = B;
            const uint32_t aWv = B + PARR;
#pragma unroll
            for (int kf = 0; kf < 4; kf++) {
                uint32_t x16[4];
                ldsm4(x16, aX + w16off + kf * 32 + rowoffA);
#pragma unroll
                for (int np = 0; np < 4; np++) {
                    uint32_t wv0[4], wv1[4];
                    ldsm4(wv0, aWv + (2 * np) * (16 * PROW) + kf * 32 + rowoffB);
                    ldsm4(wv1, aWv + (2 * np + 1) * (16 * PROW) + kf * 32 + rowoffB);
                    mma_fp16(acc[4 * np],     x16, &wv0[0]);
                    mma_fp16(acc[4 * np + 1], x16, &wv0[2]);
                    mma_fp16(acc[4 * np + 2], x16, &wv1[0]);
                    mma_fp16(acc[4 * np + 3], x16, &wv1[2]);
                }
            }
            __syncthreads();
            if (ks + 2 < 8) fillv(ks & 1, (ks + 2) * 64);
        }
    }

    // ---- epilogue (common): acc[4np+j] -> oldnf = 2*(2np + (j>>1)) + (j&1) ----
    const int r0 = m0 + w * 16 + gr;
#pragma unroll
    for (int nf = 0; nf < 16; nf++) {
        int ng;
        {
            int np = nf >> 2, j = nf & 3;
            int nfp = 2 * np + (j >> 1);
            int oldnf = 2 * nfp + (j & 1);
            ng = nb * 128 + oldnf * 8 + qt * 2;
        }
        int sel = ng >> 9;
        int within = ng & 511;
        const float* bias = (sel == 0) ? bq : (sel == 1) ? bk : bv;
        float b0 = bias[within], b1 = bias[within + 1];
        int h = within >> 6, d = within & 63;
#pragma unroll
        for (int half = 0; half < 2; half++) {
            int m = r0 + half * 8;
            int bb = m >> 11, s = m & 2047;
            float y0 = acc[nf][half * 2 + 0] + b0;
            float y1 = acc[nf][half * 2 + 1] + b1;
            if (sel < 2) {
                __nv_bfloat16 h0 = __float2bfloat16(y0);
                __nv_bfloat16 h1 = __float2bfloat16(y1);
                __nv_bfloat16 l0 = __float2bfloat16(y0 - __bfloat162float(h0));
                __nv_bfloat16 l1 = __float2bfloat16(y1 - __bfloat162float(h1));
                __nv_bfloat16* dh = (sel == 0) ? g_Qh : g_Kh;
                __nv_bfloat16* dl = (sel == 0) ? g_Ql : g_Kl;
                size_t a = (((size_t)(bb * HH + h)) * SS + s) * DD + d;
                *(uint32_t*)&dh[a] = pk2(h0, h1);
                *(uint32_t*)&dl[a] = pk2(l0, l1);
            } else {
                size_t a0 = (((size_t)(bb * HH + h)) * DD + d) * SS + s;
                g_Vth[a0]      = __float2half_rn(y0);
                g_Vth[a0 + SS] = __float2half_rn(y1);
            }
        }
    }
}

// ---------------------------------------------------------------------------
// Flash attention: S = bf16x3 (3 MMAs), PV = fp16 P x V (1 MMA).
// 128 threads (4 warps, 64 q-rows), 32-key tiles, 2-stage ring, 4 CTAs/SM.
// ---------------------------------------------------------------------------
#define NT 64
#define KROW 144
#define VROW 80
#define KARR (32*KROW)          // 4608
#define VARR (64*VROW)          // 5120
#define ASTG (2*KARR + VARR)    // 14336
#define AZT  (2*ASTG)           // 28672
#define ATTN_SMEM (AZT + SS*4)  // 36864

__global__ __launch_bounds__(128, 4) void attn_mma(float* __restrict__ out)
{
    extern __shared__ char sm[];
    const uint32_t sbase = smem_u32(sm);
    float* zts = (float*)(sm + AZT);
    const int tid = threadIdx.x;
    const int w = tid >> 5, lane = tid & 31;
    const int gr = lane >> 2, qt = lane & 3;
    const int bh = blockIdx.y;
    const int q0 = blockIdx.x * 64;

    const uint32_t rowK = (uint32_t)(((lane & 7) + ((lane >> 4) << 3)) * KROW
                                     + ((lane >> 3) & 1) * 16);
    const uint32_t rowV = (uint32_t)(((lane & 7) + ((lane >> 4) << 3)) * VROW
                                     + ((lane >> 3) & 1) * 16);

    for (int i = tid; i < SS; i += 128) zts[i] = g_zt[i];

    const int r0 = q0 + w * 16 + gr;
    const __nv_bfloat16* Qh = g_Qh + (size_t)bh * SS * DD;
    const __nv_bfloat16* Ql = g_Ql + (size_t)bh * SS * DD;
    uint32_t qah[4][4], qal[4][4];
#pragma unroll
    for (int kf = 0; kf < 4; kf++) {
        int col = kf * 16 + qt * 2;
        qah[kf][0] = *(const uint32_t*)(Qh + (size_t)r0 * 64 + col);
        qah[kf][1] = *(const uint32_t*)(Qh + (size_t)(r0 + 8) * 64 + col);
        qah[kf][2] = *(const uint32_t*)(Qh + (size_t)r0 * 64 + col + 8);
        qah[kf][3] = *(const uint32_t*)(Qh + (size_t)(r0 + 8) * 64 + col + 8);
        qal[kf][0] = *(const uint32_t*)(Ql + (size_t)r0 * 64 + col);
        qal[kf][1] = *(const uint32_t*)(Ql + (size_t)(r0 + 8) * 64 + col);
        qal[kf][2] = *(const uint32_t*)(Ql + (size_t)r0 * 64 + col + 8);
        qal[kf][3] = *(const uint32_t*)(Ql + (size_t)(r0 + 8) * 64 + col + 8);
    }

    auto fill = [&](int slot, int k0) {
        char* dstb = sm + slot * ASTG;
#pragma unroll
        for (int ii = 0; ii < 6; ii++) {
            int idx = ii * 128 + tid;       // 0..767
            int arr = idx >> 8;             // 0,1 = Kh/Kl; 2 = V
            uint32_t d;
            if (arr < 2) {
                int r = (idx >> 3) & 31, c = idx & 7;
                const __nv_bfloat16* src =
                    ((arr == 0) ? g_Kh : g_Kl) + ((size_t)bh * SS + k0 + r) * 64 + c * 8;
                d = smem_u32(dstb + arr * KARR + r * KROW + c * 16);
                CP_ASYNC16(d, src);
            } else {
                int j = idx & 255;
                int r = j >> 2, c = j & 3;
                const __half* src =
                    g_Vth + ((size_t)bh * DD + r) * SS + k0 + c * 8;
                d = smem_u32(dstb + 2 * KARR + r * VROW + c * 16);
                CP_ASYNC16(d, src);
            }
        }
        CP_COMMIT();
    };

    fill(0, 0);
    fill(1, 32);

    float O[8][4];
#pragma unroll
    for (int i = 0; i < 8; i++)
#pragma unroll
        for (int j = 0; j < 4; j++) O[i][j] = 0.f;
    float m0r = -1e30f, m1r = -1e30f, l0r = 0.f, l1r = 0.f;

#pragma unroll 1
    for (int kt = 0; kt < NT; kt++) {
        CP_WAIT1();
        __syncthreads();
        const uint32_t B    = sbase + (kt & 1) * ASTG;
        const uint32_t aKh  = B;
        const uint32_t aKl  = B + KARR;
        const uint32_t aVth = B + 2 * KARR;
        const int k0 = kt * 32;

        // ---- S = Q K^T (bf16x3), acc-major order ----
        float S[4][4];
#pragma unroll
        for (int i = 0; i < 4; i++)
#pragma unroll
            for (int j = 0; j < 4; j++) S[i][j] = 0.f;

#pragma unroll
        for (int kf = 0; kf < 4; kf++) {
            uint32_t rh0[4], rl0[4], rh1[4], rl1[4];
            ldsm4(rh0, aKh + kf * 32 + rowK);
            ldsm4(rl0, aKl + kf * 32 + rowK);
            ldsm4(rh1, aKh + 16 * KROW + kf * 32 + rowK);
            ldsm4(rl1, aKl + 16 * KROW + kf * 32 + rowK);
            mma_bf16(S[0], qah[kf], &rh0[0]); mma_bf16(S[1], qah[kf], &rh0[2]);
            mma_bf16(S[2], qah[kf], &rh1[0]); mma_bf16(S[3], qah[kf], &rh1[2]);
            mma_bf16(S[0], qah[kf], &rl0[0]); mma_bf16(S[1], qah[kf], &rl0[2]);
            mma_bf16(S[2], qah[kf], &rl1[0]); mma_bf16(S[3], qah[kf], &rl1[2]);
            mma_bf16(S[0], qal[kf], &rh0[0]); mma_bf16(S[1], qal[kf], &rh0[2]);
            mma_bf16(S[2], qal[kf], &rh1[0]); mma_bf16(S[3], qal[kf], &rh1[2]);
        }

        // ---- bias + online softmax (log2 domain, lazy rescale) ----
        float mt0 = -1e30f, mt1 = -1e30f;
#pragma unroll
        for (int nf = 0; nf < 4; nf++) {
            int c0 = k0 + nf * 8 + qt * 2;
            S[nf][0] *= zts[abs(r0 - c0)];
            S[nf][1] *= zts[abs(r0 - c0 - 1)];
            S[nf][2] *= zts[abs(r0 + 8 - c0)];
            S[nf][3] *= zts[abs(r0 + 8 - c0 - 1)];
            mt0 = fmaxf(mt0, fmaxf(S[nf][0], S[nf][1]));
            mt1 = fmaxf(mt1, fmaxf(S[nf][2], S[nf][3]));
        }
        mt0 = fmaxf(mt0, __shfl_xor_sync(0xffffffffu, mt0, 1));
        mt0 = fmaxf(mt0, __shfl_xor_sync(0xffffffffu, mt0, 2));
        mt1 = fmaxf(mt1, __shfl_xor_sync(0xffffffffu, mt1, 1));
        mt1 = fmaxf(mt1, __shfl_xor_sync(0xffffffffu, mt1, 2));
        bool changed = (mt0 > m0r) || (mt1 > m1r);
        if (__any_sync(0xffffffffu, changed)) {
            float mn0 = fmaxf(m0r, mt0), mn1 = fmaxf(m1r, mt1);
            float a0 = ex2f(m0r - mn0), a1 = ex2f(m1r - mn1);
            m0r = mn0; m1r = mn1;
            l0r *= a0; l1r *= a1;
#pragma unroll
            for (int nf = 0; nf < 8; nf++) {
                O[nf][0] *= a0; O[nf][1] *= a0;
                O[nf][2] *= a1; O[nf][3] *= a1;
            }
        }

        float s0 = 0.f, s1 = 0.f;
        uint32_t ph[2][4];
#pragma unroll
        for (int nf = 0; nf < 4; nf++) {
            float e0 = ex2f(S[nf][0] - m0r);
            float e1 = ex2f(S[nf][1] - m0r);
            float e2 = ex2f(S[nf][2] - m1r);
            float e3 = ex2f(S[nf][3] - m1r);
            s0 += e0 + e1; s1 += e2 + e3;
            uint32_t p01 = cvt_f16x2(e1, e0);
            uint32_t p23 = cvt_f16x2(e3, e2);
            int kf = nf >> 1;
            if ((nf & 1) == 0) { ph[kf][0] = p01; ph[kf][1] = p23; }
            else               { ph[kf][2] = p01; ph[kf][3] = p23; }
        }
        l0r += s0;
        l1r += s1;

        // ---- O += P V (fp16, 1 term), acc-major order ----
#pragma unroll
        for (int kf = 0; kf < 2; kf++) {
#pragma unroll
            for (int g = 0; g < 2; g++) {
                uint32_t va0[4], va1[4];
                ldsm4(va0, aVth + (2 * g) * (16 * VROW) + kf * 32 + rowV);
                ldsm4(va1, aVth + (2 * g + 1) * (16 * VROW) + kf * 32 + rowV);
                float* o0 = O[4 * g];
                float* o1 = O[4 * g + 1];
                float* o2 = O[4 * g + 2];
                float* o3 = O[4 * g + 3];
                mma_fp16(o0, ph[kf], &va0[0]); mma_fp16(o1, ph[kf], &va0[2]);
                mma_fp16(o2, ph[kf], &va1[0]); mma_fp16(o3, ph[kf], &va1[2]);
            }
        }

        __syncthreads();
        if (kt + 2 < NT) fill(kt & 1, (kt + 2) * 32);
    }

    // ---- epilogue: quad-reduce l, normalize, store ----
    l0r += __shfl_xor_sync(0xffffffffu, l0r, 1);
    l0r += __shfl_xor_sync(0xffffffffu, l0r, 2);
    l1r += __shfl_xor_sync(0xffffffffu, l1r, 1);
    l1r += __shfl_xor_sync(0xffffffffu, l1r, 2);
    float inv0 = 1.0f / l0r, inv1 = 1.0f / l1r;
    int b = bh >> 3, h = bh & 7;
#pragma unroll
    for (int nf = 0; nf < 8; nf++) {
        int g = nf >> 2, j = nf & 3;
        int oldnf = 2 * (2 * g + (j >> 1)) + (j & 1);
        int d = oldnf * 8 + qt * 2;
        float2 o0 = make_float2(O[nf][0] * inv0, O[nf][1] * inv0);
        float2 o1 = make_float2(O[nf][2] * inv1, O[nf][3] * inv1);
        *(float2*)&out[((size_t)(b * SS) + r0) * HD + h * 64 + d]       = o0;
        *(float2*)&out[((size_t)(b * SS) + r0 + 8) * HD + h * 64 + d]   = o1;
    }
}

// ---------------------------------------------------------------------------
extern "C" void kernel_launch(void* const* d_in, const int* in_sizes, int n_in,
                              void* d_out, int out_size)
{
    const float* x  = (const float*)d_in[0];
    const float* Wq = (const float*)d_in[1];
    const float* bq = (const float*)d_in[2];
    const float* Wk = (const float*)d_in[3];
    const float* bk = (const float*)d_in[4];
    const float* Wv = (const float*)d_in[5];
    const float* bv = (const float*)d_in[6];
    const float* ah = (const float*)d_in[7];
    const float* vh = (const float*)d_in[8];
    float* out = (float*)d_out;

    zhat_kernel<<<SS / 256, 256>>>(ah, vh);
    split_kernel<<<(NX8 + 3 * NW8_1) / 256, 256>>>(x, Wq, Wk, Wv);

    cudaFuncSetAttribute(proj_mma,
                         cudaFuncAttributeMaxDynamicSharedMemorySize, PROJ_SMEM);
    proj_mma<<<dim3(12, 64), 256, PROJ_SMEM>>>(bq, bk, bv);

    cudaFuncSetAttribute(attn_mma,
                         cudaFuncAttributeMaxDynamicSharedMemorySize, ATTN_SMEM);
    attn_mma<<<dim3(SS / 64, BB * HH), 128, ATTN_SMEM>>>(out);
}